// round 5
// baseline (speedup 1.0000x reference)
#include <cuda_runtime.h>
#include <cuda_fp16.h>
#include <cstdint>

#define NNODES 100000
#define NEDGES 1600000
#define NFEAT 48
#define HID 128
#define NTILES (NEDGES / 128)   // 12500 exactly

// Scratch (no allocation allowed): 19.2MB msum + 400KB cnt
__device__ float g_msum[(size_t)NNODES * NFEAT];
__device__ float g_cnt[NNODES];
__device__ int g_stride;   // edge_index word stride: 2 = int64 storage, 1 = int32

// ---------------- SMEM layout (bytes) ----------------
#define ESTRIDE 272              // 128 fp16 cols padded +16B -> conflict-free ldmatrix
#define H3STRIDE 208             // 48 f32 cols padded +16B
#define SM_SRC 0                 // 128 x int32
#define SM_TGT 512               // 128 x int32
#define SM_B1 1024               // 128 x f32
#define SM_B2 1536               // 128 x f32
#define SM_B3 2048               // 48 x f32 (256B slot)
#define SM_E  2304               // 128 rows x ESTRIDE
#define SM_W1 (SM_E + 128 * ESTRIDE)     // W1^T [128n][128k] fp16 padded
#define SM_W2 (SM_W1 + 128 * ESTRIDE)
#define SM_W3 (SM_W2 + 128 * ESTRIDE)    // 48 rows
#define SM_H3 (SM_W3 + 48 * ESTRIDE)     // 128 rows x H3STRIDE f32
#define SMEM_TOTAL (SM_H3 + 128 * H3STRIDE)   // 146432 bytes

// ---------------- helpers ----------------
__device__ __forceinline__ uint32_t smem_to_u32(const void* p) {
    uint32_t a;
    asm("{ .reg .u64 t; cvta.to.shared.u64 t, %1; cvt.u32.u64 %0, t; }" : "=r"(a) : "l"(p));
    return a;
}

__device__ __forceinline__ void ldsm_x4(uint32_t& r0, uint32_t& r1, uint32_t& r2, uint32_t& r3,
                                        uint32_t addr) {
    asm volatile("ldmatrix.sync.aligned.m8n8.x4.shared.b16 {%0,%1,%2,%3}, [%4];"
                 : "=r"(r0), "=r"(r1), "=r"(r2), "=r"(r3) : "r"(addr));
}
__device__ __forceinline__ void ldsm_x2(uint32_t& r0, uint32_t& r1, uint32_t addr) {
    asm volatile("ldmatrix.sync.aligned.m8n8.x2.shared.b16 {%0,%1}, [%2];"
                 : "=r"(r0), "=r"(r1) : "r"(addr));
}

__device__ __forceinline__ void mma_f16(float c[4], uint32_t a0, uint32_t a1, uint32_t a2,
                                        uint32_t a3, uint32_t b0, uint32_t b1) {
    asm volatile(
        "mma.sync.aligned.m16n8k16.row.col.f32.f16.f16.f32 "
        "{%0,%1,%2,%3}, {%4,%5,%6,%7}, {%8,%9}, {%0,%1,%2,%3};"
        : "+f"(c[0]), "+f"(c[1]), "+f"(c[2]), "+f"(c[3])
        : "r"(a0), "r"(a1), "r"(a2), "r"(a3), "r"(b0), "r"(b1));
}

__device__ __forceinline__ uint32_t pk2(float a, float b) {
    __half2 h = __floats2half2_rn(a, b);
    return *reinterpret_cast<uint32_t*>(&h);
}

__device__ __forceinline__ void red_add_v4(float* p, float a, float b, float c, float d) {
    asm volatile("red.global.add.v4.f32 [%0], {%1, %2, %3, %4};"
                 :: "l"(p), "f"(a), "f"(b), "f"(c), "f"(d) : "memory");
}

// ---------------- kernels ----------------

// Detect edge_index storage width. If truly int64, all odd 32-bit words of the
// first 256 elements are zero (values in [0,1e5), nonneg). If int32 (JAX default
// with x64 disabled downcasts), odd words are random indices.
__global__ void detect_kernel(const int* __restrict__ ei32) {
    if (threadIdx.x == 0 && blockIdx.x == 0) {
        int odd_or = 0;
        #pragma unroll 8
        for (int i = 0; i < 256; i++) odd_or |= ei32[2 * i + 1];
        g_stride = odd_or ? 1 : 2;
    }
}

__global__ void zero_kernel() {
    int n = NNODES * NFEAT;
    for (int i = blockIdx.x * blockDim.x + threadIdx.x; i < n; i += gridDim.x * blockDim.x) {
        g_msum[i] = 0.0f;
        if (i < NNODES) g_cnt[i] = 0.0f;
    }
}

__global__ void __launch_bounds__(256, 1)
gnn_fused_kernel(const float* __restrict__ x, const int* __restrict__ ei32,
                 const float* __restrict__ efeat,
                 const float* __restrict__ W1, const float* __restrict__ b1,
                 const float* __restrict__ W2, const float* __restrict__ b2,
                 const float* __restrict__ W3, const float* __restrict__ b3) {
    extern __shared__ char smem[];
    const uint32_t sb = smem_to_u32(smem);
    const int tid = threadIdx.x;
    const int w = tid >> 5;
    const int l = tid & 31;
    const long long stride = (long long)g_stride;

    // ---- one-time init: zero E + weight tiles (pad regions must be 0) ----
    for (int i = tid; i < (SM_H3 - SM_E) / 16; i += 256)
        reinterpret_cast<uint4*>(smem + SM_E)[i] = make_uint4(0, 0, 0, 0);
    __syncthreads();

    // Weights transposed: Wt[n][k] = W[k][n], fp16, row stride ESTRIDE.
    for (int idx = tid; idx < 112 * HID; idx += 256) {
        int k = idx >> 7, n = idx & 127;   // coalesced over n
        *reinterpret_cast<__half*>(smem + SM_W1 + n * ESTRIDE + k * 2) =
            __float2half(W1[idx]);
    }
    for (int idx = tid; idx < HID * HID; idx += 256) {
        int k = idx >> 7, n = idx & 127;
        *reinterpret_cast<__half*>(smem + SM_W2 + n * ESTRIDE + k * 2) =
            __float2half(W2[idx]);
    }
    for (int idx = tid; idx < HID * NFEAT; idx += 256) {
        int k = idx / NFEAT, n = idx - k * NFEAT;
        *reinterpret_cast<__half*>(smem + SM_W3 + n * ESTRIDE + k * 2) =
            __float2half(W3[idx]);
    }
    if (tid < HID) {
        reinterpret_cast<float*>(smem + SM_B1)[tid] = b1[tid];
        reinterpret_cast<float*>(smem + SM_B2)[tid] = b2[tid];
    }
    if (tid < NFEAT) reinterpret_cast<float*>(smem + SM_B3)[tid] = b3[tid];

    const float* sB1 = reinterpret_cast<const float*>(smem + SM_B1);
    const float* sB2 = reinterpret_cast<const float*>(smem + SM_B2);
    const float* sB3 = reinterpret_cast<const float*>(smem + SM_B3);
    const int* sSrc = reinterpret_cast<const int*>(smem + SM_SRC);
    const int* sTgt = reinterpret_cast<const int*>(smem + SM_TGT);

    // per-lane ldmatrix base addresses
    // A (E tile): lanes 0-7 rows 0-7 @klo, 8-15 rows 8-15 @klo, 16-23 rows 0-7 @khi, 24-31 rows 8-15 @khi
    const uint32_t ebase = sb + SM_E + (uint32_t)(16 * w + (l & 15)) * ESTRIDE + ((l >> 4) << 4);
    // B (Wt): lanes 0-7 rows n0-7 @klo, lanes 8-15 rows n0-7 @khi
    const uint32_t woff = (uint32_t)(l & 7) * ESTRIDE + (((l >> 3) & 1) << 4);
    const uint32_t wb1 = sb + SM_W1 + woff;
    const uint32_t wb2 = sb + SM_W2 + woff;
    const uint32_t wb3 = sb + SM_W3 + woff;

    for (int tile = blockIdx.x; tile < NTILES; tile += gridDim.x) {
        const long long base = (long long)tile * 128;

        __syncthreads();   // protect SRC/TGT/E/H3 from previous iteration's readers
        if (tid < 128) {
            // Low 32-bit word of element e lives at word index stride*e (LE).
            int s = ei32[stride * (base + tid)];
            int t = ei32[stride * (NEDGES + base + tid)];
            s = min(max(s, 0), NNODES - 1);
            t = min(max(t, 0), NNODES - 1);
            reinterpret_cast<int*>(smem + SM_SRC)[tid] = s;
            reinterpret_cast<int*>(smem + SM_TGT)[tid] = t;
        }
        __syncthreads();

        // ---- gather + concat -> fp16 E tile (coalesced by row fragments) ----
        // flat float4 index f: row = f/28, q = f%28 (28 float4 per 112-float row)
        #pragma unroll
        for (int j = 0; j < 14; j++) {
            int f = j * 256 + tid;
            int row = f / 28;
            int q = f - row * 28;
            const float4* p;
            if (q < 12)      p = reinterpret_cast<const float4*>(x + (size_t)sSrc[row] * NFEAT) + q;
            else if (q < 24) p = reinterpret_cast<const float4*>(x + (size_t)sTgt[row] * NFEAT) + (q - 12);
            else             p = reinterpret_cast<const float4*>(efeat + (size_t)(base + row) * 16) + (q - 24);
            float4 v = *p;
            uint2 pk;
            pk.x = pk2(v.x, v.y);
            pk.y = pk2(v.z, v.w);
            *reinterpret_cast<uint2*>(smem + SM_E + row * ESTRIDE + q * 8) = pk;
        }
        __syncthreads();

        // ---- Layer 1: h1 = relu(E @ W1^T + b1), per-warp 16 rows ----
        float a1[16][4];
        #pragma unroll
        for (int t = 0; t < 16; t++) { a1[t][0] = a1[t][1] = a1[t][2] = a1[t][3] = 0.0f; }
        #pragma unroll
        for (int j = 0; j < 8; j++) {
            uint32_t A0, A1, A2, A3;
            ldsm_x4(A0, A1, A2, A3, ebase + 32 * j);
            #pragma unroll
            for (int t = 0; t < 16; t++) {
                uint32_t B0, B1;
                ldsm_x2(B0, B1, wb1 + (uint32_t)t * (8 * ESTRIDE) + 32 * j);
                mma_f16(a1[t], A0, A1, A2, A3, B0, B1);
            }
        }
        uint32_t h1[32];
        {
            const int cb = 2 * (l & 3);
            #pragma unroll
            for (int t = 0; t < 16; t++) {
                float bx = sB1[8 * t + cb], by = sB1[8 * t + cb + 1];
                h1[2 * t]     = pk2(fmaxf(a1[t][0] + bx, 0.f), fmaxf(a1[t][1] + by, 0.f));
                h1[2 * t + 1] = pk2(fmaxf(a1[t][2] + bx, 0.f), fmaxf(a1[t][3] + by, 0.f));
            }
        }

        // ---- Layer 2: h2 = relu(h1 @ W2^T + b2); A-fragments = packed accums ----
        float a2[16][4];
        #pragma unroll
        for (int t = 0; t < 16; t++) { a2[t][0] = a2[t][1] = a2[t][2] = a2[t][3] = 0.0f; }
        #pragma unroll
        for (int j = 0; j < 8; j++) {
            #pragma unroll
            for (int t = 0; t < 16; t++) {
                uint32_t B0, B1;
                ldsm_x2(B0, B1, wb2 + (uint32_t)t * (8 * ESTRIDE) + 32 * j);
                mma_f16(a2[t], h1[4 * j], h1[4 * j + 1], h1[4 * j + 2], h1[4 * j + 3], B0, B1);
            }
        }
        uint32_t h2[32];
        {
            const int cb = 2 * (l & 3);
            #pragma unroll
            for (int t = 0; t < 16; t++) {
                float bx = sB2[8 * t + cb], by = sB2[8 * t + cb + 1];
                h2[2 * t]     = pk2(fmaxf(a2[t][0] + bx, 0.f), fmaxf(a2[t][1] + by, 0.f));
                h2[2 * t + 1] = pk2(fmaxf(a2[t][2] + bx, 0.f), fmaxf(a2[t][3] + by, 0.f));
            }
        }

        // ---- Layer 3: msg = h2 @ W3^T + b3 (N = 48) ----
        float a3[6][4];
        #pragma unroll
        for (int t = 0; t < 6; t++) { a3[t][0] = a3[t][1] = a3[t][2] = a3[t][3] = 0.0f; }
        #pragma unroll
        for (int j = 0; j < 8; j++) {
            #pragma unroll
            for (int t = 0; t < 6; t++) {
                uint32_t B0, B1;
                ldsm_x2(B0, B1, wb3 + (uint32_t)t * (8 * ESTRIDE) + 32 * j);
                mma_f16(a3[t], h2[4 * j], h2[4 * j + 1], h2[4 * j + 2], h2[4 * j + 3], B0, B1);
            }
        }

        // ---- write msg fragments (+b3) to SMEM H3 for contiguous scatter ----
        {
            const int cb = 2 * (l & 3);
            char* h3r0 = smem + SM_H3 + (16 * w + (l >> 2)) * H3STRIDE;
            char* h3r1 = h3r0 + 8 * H3STRIDE;
            #pragma unroll
            for (int t = 0; t < 6; t++) {
                float bx = sB3[8 * t + cb], by = sB3[8 * t + cb + 1];
                *reinterpret_cast<float2*>(h3r0 + (8 * t + cb) * 4) =
                    make_float2(a3[t][0] + bx, a3[t][1] + by);
                *reinterpret_cast<float2*>(h3r1 + (8 * t + cb) * 4) =
                    make_float2(a3[t][2] + bx, a3[t][3] + by);
            }
        }
        __syncthreads();

        // ---- scatter: 6 x red.v4 per half-row + count ----
        {
            int row = tid >> 1, half = tid & 1;
            const float4* hp = reinterpret_cast<const float4*>(smem + SM_H3 + row * H3STRIDE) + half * 6;
            int tgt = sTgt[row];
            float* dst = g_msum + (size_t)tgt * NFEAT + half * 24;
            #pragma unroll
            for (int i = 0; i < 6; i++) {
                float4 v = hp[i];
                red_add_v4(dst + 4 * i, v.x, v.y, v.z, v.w);
            }
            if (half == 0)
                asm volatile("red.global.add.f32 [%0], %1;" :: "l"(g_cnt + tgt), "f"(1.0f) : "memory");
        }
    }
}

__global__ void finalize_kernel(const float* __restrict__ x, float* __restrict__ out) {
    int i = blockIdx.x * blockDim.x + threadIdx.x;
    if (i < NNODES * NFEAT) {
        int node = i / NFEAT;
        out[i] = x[i] + g_msum[i] / fmaxf(g_cnt[node], 1.0f);
    }
}

// ---------------- launch ----------------
extern "C" void kernel_launch(void* const* d_in, const int* in_sizes, int n_in,
                              void* d_out, int out_size) {
    const float* x  = (const float*)d_in[0];
    const int*   ei = (const int*)d_in[1];
    const float* ef = (const float*)d_in[2];
    const float* W1 = (const float*)d_in[3];
    const float* b1 = (const float*)d_in[4];
    const float* W2 = (const float*)d_in[5];
    const float* b2 = (const float*)d_in[6];
    const float* W3 = (const float*)d_in[7];
    const float* b3 = (const float*)d_in[8];

    cudaFuncSetAttribute(gnn_fused_kernel,
                         cudaFuncAttributeMaxDynamicSharedMemorySize, SMEM_TOTAL);

    detect_kernel<<<1, 32>>>(ei);
    zero_kernel<<<1024, 256>>>();
    gnn_fused_kernel<<<148, 256, SMEM_TOTAL>>>(x, ei, ef, W1, b1, W2, b2, W3, b3);
    finalize_kernel<<<(NNODES * NFEAT + 255) / 256, 256>>>(x, (float*)d_out);
}

// round 6
// speedup vs baseline: 1.9355x; 1.9355x over previous
#include <cuda_runtime.h>
#include <cuda_fp16.h>
#include <cstdint>

#define NNODES 100000
#define NEDGES 1600000
#define NFEAT 48
#define HID 128
#define NTILES (NEDGES / 128)   // 12500 exactly

// Scratch (no allocation allowed): 19.2MB msum + 400KB cnt
__device__ float g_msum[(size_t)NNODES * NFEAT];
__device__ float g_cnt[NNODES];
__device__ int g_stride;   // edge_index word stride: 2 = int64 storage, 1 = int32

// ---------------- SMEM layout (bytes) ----------------
#define ESTRIDE 272              // 128 fp16 cols padded +16B -> conflict-free ldmatrix
#define SM_SRC0 0                // 128 x int32
#define SM_TGT0 512
#define SM_SRC1 1024
#define SM_TGT1 1536
#define SM_B1   2048             // 128 x f32
#define SM_B2   2560
#define SM_B3   3072             // 48 x f32 (256B slot)
#define SM_E    3328             // 128 rows x ESTRIDE fp16 (34816)
#define SM_W1   (SM_E + 128 * ESTRIDE)    // 38144
#define SM_W2   (SM_W1 + 128 * ESTRIDE)   // 72960
#define SM_W3   (SM_W2 + 128 * ESTRIDE)   // 107776 (48 rows -> 13056)
#define SM_STAGE (SM_W3 + 48 * ESTRIDE)   // 120832, flat fp32 gather stage
#define SMEM_TOTAL (SM_STAGE + 128 * 112 * 4)   // 178176 bytes

// ---------------- helpers ----------------
__device__ __forceinline__ uint32_t smem_to_u32(const void* p) {
    uint32_t a;
    asm("{ .reg .u64 t; cvta.to.shared.u64 t, %1; cvt.u32.u64 %0, t; }" : "=r"(a) : "l"(p));
    return a;
}

__device__ __forceinline__ void ldsm_x4(uint32_t& r0, uint32_t& r1, uint32_t& r2, uint32_t& r3,
                                        uint32_t addr) {
    asm volatile("ldmatrix.sync.aligned.m8n8.x4.shared.b16 {%0,%1,%2,%3}, [%4];"
                 : "=r"(r0), "=r"(r1), "=r"(r2), "=r"(r3) : "r"(addr));
}

__device__ __forceinline__ void mma_f16(float c[4], uint32_t a0, uint32_t a1, uint32_t a2,
                                        uint32_t a3, uint32_t b0, uint32_t b1) {
    asm volatile(
        "mma.sync.aligned.m16n8k16.row.col.f32.f16.f16.f32 "
        "{%0,%1,%2,%3}, {%4,%5,%6,%7}, {%8,%9}, {%0,%1,%2,%3};"
        : "+f"(c[0]), "+f"(c[1]), "+f"(c[2]), "+f"(c[3])
        : "r"(a0), "r"(a1), "r"(a2), "r"(a3), "r"(b0), "r"(b1));
}

__device__ __forceinline__ uint32_t pk2(float a, float b) {
    __half2 h = __floats2half2_rn(a, b);
    return *reinterpret_cast<uint32_t*>(&h);
}

__device__ __forceinline__ void red_add_v2(float* p, float a, float b) {
    asm volatile("red.global.add.v2.f32 [%0], {%1, %2};"
                 :: "l"(p), "f"(a), "f"(b) : "memory");
}

__device__ __forceinline__ void cp16(uint32_t dst, const void* src) {
    asm volatile("cp.async.cg.shared.global [%0], [%1], 16;" :: "r"(dst), "l"(src) : "memory");
}

// Issue the full gather for one tile as cp.async into the flat stage buffer.
__device__ __forceinline__ void issue_gather(uint32_t sb, const int* sSrc, const int* sTgt,
                                             const float* x, const float* efeat,
                                             long long base, int tid) {
    #pragma unroll
    for (int j = 0; j < 14; j++) {
        int f = j * 256 + tid;
        int row = f / 28;
        int q = f - row * 28;
        const float4* p;
        if (q < 12)      p = reinterpret_cast<const float4*>(x + (size_t)sSrc[row] * NFEAT) + q;
        else if (q < 24) p = reinterpret_cast<const float4*>(x + (size_t)sTgt[row] * NFEAT) + (q - 12);
        else             p = reinterpret_cast<const float4*>(efeat + (size_t)(base + row) * 16) + (q - 24);
        cp16(sb + SM_STAGE + f * 16, p);
    }
}

// ---------------- kernels ----------------

// Detect edge_index storage width (int64 vs downcast int32; see R3 notes).
__global__ void detect_kernel(const int* __restrict__ ei32) {
    if (threadIdx.x == 0 && blockIdx.x == 0) {
        int odd_or = 0;
        #pragma unroll 8
        for (int i = 0; i < 256; i++) odd_or |= ei32[2 * i + 1];
        g_stride = odd_or ? 1 : 2;
    }
}

__global__ void zero_kernel() {
    int n4 = NNODES * NFEAT / 4;
    float4 z = make_float4(0.f, 0.f, 0.f, 0.f);
    for (int i = blockIdx.x * blockDim.x + threadIdx.x; i < n4; i += gridDim.x * blockDim.x) {
        reinterpret_cast<float4*>(g_msum)[i] = z;
        if (i < NNODES) g_cnt[i] = 0.0f;
    }
}

__global__ void __launch_bounds__(256, 1)
gnn_fused_kernel(const float* __restrict__ x, const int* __restrict__ ei32,
                 const float* __restrict__ efeat,
                 const float* __restrict__ W1, const float* __restrict__ b1,
                 const float* __restrict__ W2, const float* __restrict__ b2,
                 const float* __restrict__ W3, const float* __restrict__ b3) {
    extern __shared__ char smem[];
    const uint32_t sb = smem_to_u32(smem);
    const int tid = threadIdx.x;
    const int w = tid >> 5;
    const int l = tid & 31;
    const long long stride = (long long)g_stride;

    // ---- one-time init: zero E + weight tiles (pad regions must be 0) ----
    for (int i = tid; i < (SM_STAGE - SM_E) / 16; i += 256)
        reinterpret_cast<uint4*>(smem + SM_E)[i] = make_uint4(0, 0, 0, 0);
    __syncthreads();

    // Weights transposed: Wt[n][k] = W[k][n], fp16, row stride ESTRIDE.
    for (int idx = tid; idx < 112 * HID; idx += 256) {
        int k = idx >> 7, n = idx & 127;
        *reinterpret_cast<__half*>(smem + SM_W1 + n * ESTRIDE + k * 2) = __float2half(W1[idx]);
    }
    for (int idx = tid; idx < HID * HID; idx += 256) {
        int k = idx >> 7, n = idx & 127;
        *reinterpret_cast<__half*>(smem + SM_W2 + n * ESTRIDE + k * 2) = __float2half(W2[idx]);
    }
    for (int idx = tid; idx < HID * NFEAT; idx += 256) {
        int k = idx / NFEAT, n = idx - k * NFEAT;
        *reinterpret_cast<__half*>(smem + SM_W3 + n * ESTRIDE + k * 2) = __float2half(W3[idx]);
    }
    if (tid < HID) {
        reinterpret_cast<float*>(smem + SM_B1)[tid] = b1[tid];
        reinterpret_cast<float*>(smem + SM_B2)[tid] = b2[tid];
    }
    if (tid < NFEAT) reinterpret_cast<float*>(smem + SM_B3)[tid] = b3[tid];
    __syncthreads();

    const float* sB1 = reinterpret_cast<const float*>(smem + SM_B1);
    const float* sB2 = reinterpret_cast<const float*>(smem + SM_B2);
    const float* sB3 = reinterpret_cast<const float*>(smem + SM_B3);

    // ldmatrix lane addressing.
    // A (E tile), x4: lanes 0-7 rows 0-7 @klo, 8-15 rows 8-15 @klo, 16-23 rows 0-7 @khi, 24-31 rows 8-15 @khi
    const uint32_t ebase = sb + SM_E + (uint32_t)(16 * w + (l & 15)) * ESTRIDE + ((l >> 4) << 4);
    // B (Wt), x4 over TWO n-tiles: g=l>>3: g0=t klo, g1=t khi, g2=t+1 klo, g3=t+1 khi
    const uint32_t woff4 = (uint32_t)(l & 7) * ESTRIDE + (((l >> 3) & 1) << 4)
                         + (uint32_t)(l >> 4) * (8 * ESTRIDE);
    const uint32_t wb1 = sb + SM_W1 + woff4;
    const uint32_t wb2 = sb + SM_W2 + woff4;
    const uint32_t wb3 = sb + SM_W3 + woff4;

    // Hoisted layer-3 bias (lane-constant across tiles).
    const int cb = 2 * (l & 3);
    float bx3[6], by3[6];
    #pragma unroll
    for (int t = 0; t < 6; t++) { bx3[t] = sB3[8 * t + cb]; by3[t] = sB3[8 * t + cb + 1]; }

    // ---- prologue: indices + gather for first tile ----
    int cur = 0;
    {
        long long e = (long long)blockIdx.x * 128 + tid;
        if (tid < 128) {
            int s = ei32[stride * e];
            int t = ei32[stride * (NEDGES + e)];
            reinterpret_cast<int*>(smem + SM_SRC0)[tid] = min(max(s, 0), NNODES - 1);
            reinterpret_cast<int*>(smem + SM_TGT0)[tid] = min(max(t, 0), NNODES - 1);
        }
        __syncthreads();
        issue_gather(sb, reinterpret_cast<const int*>(smem + SM_SRC0),
                     reinterpret_cast<const int*>(smem + SM_TGT0),
                     x, efeat, (long long)blockIdx.x * 128, tid);
        asm volatile("cp.async.commit_group;" ::: "memory");
    }

    for (int tile = blockIdx.x; tile < NTILES; tile += gridDim.x) {
        const int next = tile + gridDim.x;
        const int* sSrcC = reinterpret_cast<const int*>(smem + (cur ? SM_SRC1 : SM_SRC0));
        const int* sTgtC = reinterpret_cast<const int*>(smem + (cur ? SM_TGT1 : SM_TGT0));
        int* sSrcN = reinterpret_cast<int*>(smem + (cur ? SM_SRC0 : SM_SRC1));
        int* sTgtN = reinterpret_cast<int*>(smem + (cur ? SM_TGT0 : SM_TGT1));

        // ---- stage ready: convert fp32 stage -> fp16 E tile (own fragments only) ----
        asm volatile("cp.async.wait_group 0;" ::: "memory");
        #pragma unroll
        for (int j = 0; j < 14; j++) {
            int f = j * 256 + tid;
            int row = f / 28;
            int q = f - row * 28;
            float4 v = reinterpret_cast<const float4*>(smem + SM_STAGE)[f];
            uint2 pk;
            pk.x = pk2(v.x, v.y);
            pk.y = pk2(v.z, v.w);
            *reinterpret_cast<uint2*>(smem + SM_E + row * ESTRIDE + q * 8) = pk;
        }
        __syncthreads();   // E visible to all warps; stage free

        // ---- prefetch next tile's indices under layer 1 ----
        int nsrc = 0, ntgt = 0;
        if (next < NTILES && tid < 128) {
            long long e = (long long)next * 128 + tid;
            nsrc = ei32[stride * e];
            ntgt = ei32[stride * (NEDGES + e)];
        }

        // ---- Layer 1: h1 = relu(E @ W1^T + b1), per-warp 16 rows ----
        float a1[16][4];
        #pragma unroll
        for (int t = 0; t < 16; t++) { a1[t][0] = a1[t][1] = a1[t][2] = a1[t][3] = 0.0f; }
        #pragma unroll
        for (int j = 0; j < 8; j++) {
            uint32_t A0, A1, A2, A3;
            ldsm_x4(A0, A1, A2, A3, ebase + 32 * j);
            #pragma unroll
            for (int t = 0; t < 16; t += 2) {
                uint32_t B0, B1, B2, B3;
                ldsm_x4(B0, B1, B2, B3, wb1 + (uint32_t)t * (8 * ESTRIDE) + 32 * j);
                mma_f16(a1[t],     A0, A1, A2, A3, B0, B1);
                mma_f16(a1[t + 1], A0, A1, A2, A3, B2, B3);
            }
        }
        uint32_t h1[32];
        #pragma unroll
        for (int t = 0; t < 16; t++) {
            float bx = sB1[8 * t + cb], by = sB1[8 * t + cb + 1];
            h1[2 * t]     = pk2(fmaxf(a1[t][0] + bx, 0.f), fmaxf(a1[t][1] + by, 0.f));
            h1[2 * t + 1] = pk2(fmaxf(a1[t][2] + bx, 0.f), fmaxf(a1[t][3] + by, 0.f));
        }

        // ---- store next indices, sync, kick off next gather ----
        if (next < NTILES && tid < 128) {
            sSrcN[tid] = min(max(nsrc, 0), NNODES - 1);
            sTgtN[tid] = min(max(ntgt, 0), NNODES - 1);
        }
        __syncthreads();   // idx visible; all warps done reading E (layer 1)
        if (next < NTILES)
            issue_gather(sb, sSrcN, sTgtN, x, efeat, (long long)next * 128, tid);
        asm volatile("cp.async.commit_group;" ::: "memory");

        // ---- Layer 2: h2 = relu(h1 @ W2^T + b2) ----
        float a2[16][4];
        #pragma unroll
        for (int t = 0; t < 16; t++) { a2[t][0] = a2[t][1] = a2[t][2] = a2[t][3] = 0.0f; }
        #pragma unroll
        for (int j = 0; j < 8; j++) {
            #pragma unroll
            for (int t = 0; t < 16; t += 2) {
                uint32_t B0, B1, B2, B3;
                ldsm_x4(B0, B1, B2, B3, wb2 + (uint32_t)t * (8 * ESTRIDE) + 32 * j);
                mma_f16(a2[t],     h1[4 * j], h1[4 * j + 1], h1[4 * j + 2], h1[4 * j + 3], B0, B1);
                mma_f16(a2[t + 1], h1[4 * j], h1[4 * j + 1], h1[4 * j + 2], h1[4 * j + 3], B2, B3);
            }
        }
        uint32_t h2[32];
        #pragma unroll
        for (int t = 0; t < 16; t++) {
            float bx = sB2[8 * t + cb], by = sB2[8 * t + cb + 1];
            h2[2 * t]     = pk2(fmaxf(a2[t][0] + bx, 0.f), fmaxf(a2[t][1] + by, 0.f));
            h2[2 * t + 1] = pk2(fmaxf(a2[t][2] + bx, 0.f), fmaxf(a2[t][3] + by, 0.f));
        }

        // ---- Layer 3: msg = h2 @ W3^T + b3 (N = 48) ----
        float a3[6][4];
        #pragma unroll
        for (int t = 0; t < 6; t++) { a3[t][0] = a3[t][1] = a3[t][2] = a3[t][3] = 0.0f; }
        #pragma unroll
        for (int j = 0; j < 8; j++) {
            #pragma unroll
            for (int t = 0; t < 6; t += 2) {
                uint32_t B0, B1, B2, B3;
                ldsm_x4(B0, B1, B2, B3, wb3 + (uint32_t)t * (8 * ESTRIDE) + 32 * j);
                mma_f16(a3[t],     h2[4 * j], h2[4 * j + 1], h2[4 * j + 2], h2[4 * j + 3], B0, B1);
                mma_f16(a3[t + 1], h2[4 * j], h2[4 * j + 1], h2[4 * j + 2], h2[4 * j + 3], B2, B3);
            }
        }

        // ---- direct register scatter: rows r0=(16w + l>>2), r1=r0+8 ----
        {
            int r0 = 16 * w + (l >> 2), r1 = r0 + 8;
            int tgt0 = sTgtC[r0], tgt1 = sTgtC[r1];
            float* d0 = g_msum + (size_t)tgt0 * NFEAT + cb;
            float* d1 = g_msum + (size_t)tgt1 * NFEAT + cb;
            #pragma unroll
            for (int t = 0; t < 6; t++) {
                red_add_v2(d0 + 8 * t, a3[t][0] + bx3[t], a3[t][1] + by3[t]);
                red_add_v2(d1 + 8 * t, a3[t][2] + bx3[t], a3[t][3] + by3[t]);
            }
            if ((l & 3) == 0) {
                asm volatile("red.global.add.f32 [%0], %1;" :: "l"(g_cnt + tgt0), "f"(1.0f) : "memory");
                asm volatile("red.global.add.f32 [%0], %1;" :: "l"(g_cnt + tgt1), "f"(1.0f) : "memory");
            }
        }
        cur ^= 1;
    }
}

__global__ void finalize_kernel(const float* __restrict__ x, float* __restrict__ out) {
    int i = blockIdx.x * blockDim.x + threadIdx.x;
    int n4 = NNODES * NFEAT / 4;
    if (i < n4) {
        int node = i / 12;   // 12 float4 per node (48 feats)
        float inv = __fdividef(1.0f, fmaxf(g_cnt[node], 1.0f));
        float4 m = reinterpret_cast<const float4*>(g_msum)[i];
        float4 xv = reinterpret_cast<const float4*>(x)[i];
        float4 o;
        o.x = xv.x + m.x * inv;
        o.y = xv.y + m.y * inv;
        o.z = xv.z + m.z * inv;
        o.w = xv.w + m.w * inv;
        reinterpret_cast<float4*>(out)[i] = o;
    }
}

// ---------------- launch ----------------
extern "C" void kernel_launch(void* const* d_in, const int* in_sizes, int n_in,
                              void* d_out, int out_size) {
    const float* x  = (const float*)d_in[0];
    const int*   ei = (const int*)d_in[1];
    const float* ef = (const float*)d_in[2];
    const float* W1 = (const float*)d_in[3];
    const float* b1 = (const float*)d_in[4];
    const float* W2 = (const float*)d_in[5];
    const float* b2 = (const float*)d_in[6];
    const float* W3 = (const float*)d_in[7];
    const float* b3 = (const float*)d_in[8];

    cudaFuncSetAttribute(gnn_fused_kernel,
                         cudaFuncAttributeMaxDynamicSharedMemorySize, SMEM_TOTAL);

    detect_kernel<<<1, 32>>>(ei);
    zero_kernel<<<1024, 256>>>();
    gnn_fused_kernel<<<148, 256, SMEM_TOTAL>>>(x, ei, ef, W1, b1, W2, b2, W3, b3);
    finalize_kernel<<<(NNODES * NFEAT / 4 + 255) / 256, 256>>>(x, (float*)d_out);
}

// round 8
// speedup vs baseline: 2.0681x; 1.0685x over previous
#include <cuda_runtime.h>
#include <cuda_fp16.h>
#include <cstdint>

#define NNODES 100000
#define NEDGES 1600000
#define NFEAT 48
#define HID 128
#define NTILES (NEDGES / 128)   // 12500 exactly

// Scratch (no allocation allowed): 19.2MB msum + 400KB cnt
__device__ float g_msum[(size_t)NNODES * NFEAT];
__device__ float g_cnt[NNODES];
__device__ int g_stride;   // edge_index word stride: 2 = int64 storage, 1 = int32

// ---------------- SMEM layout (bytes) ----------------
#define ESTRIDE 272               // weight rows: 128 fp16 cols padded +16B (conflict-free ldsm)
#define SSTRIDE 464               // stage rows: 112 f32 + 4 pad floats (16B-aligned, bank-spread)
#define SM_SRC0 0                 // 128 x int32
#define SM_TGT0 512
#define SM_SRC1 1024
#define SM_TGT1 1536
#define SM_B1   2048              // 128 x f32
#define SM_B2   2560
#define SM_B3   3072              // 48 x f32 (256B slot)
#define SM_W1   3328                       // 128 rows
#define SM_W2   (SM_W1 + 128 * ESTRIDE)    // 38144
#define SM_W3   (SM_W2 + 128 * ESTRIDE)    // 72960 (48 rows)
#define SM_STAGE (SM_W3 + 48 * ESTRIDE)    // 86016, fp32 gather stage 128 x SSTRIDE
#define SMEM_TOTAL (SM_STAGE + 128 * SSTRIDE)   // 145408 bytes

// ---------------- helpers ----------------
__device__ __forceinline__ uint32_t smem_to_u32(const void* p) {
    uint32_t a;
    asm("{ .reg .u64 t; cvta.to.shared.u64 t, %1; cvt.u32.u64 %0, t; }" : "=r"(a) : "l"(p));
    return a;
}

__device__ __forceinline__ void ldsm_x4(uint32_t& r0, uint32_t& r1, uint32_t& r2, uint32_t& r3,
                                        uint32_t addr) {
    asm volatile("ldmatrix.sync.aligned.m8n8.x4.shared.b16 {%0,%1,%2,%3}, [%4];"
                 : "=r"(r0), "=r"(r1), "=r"(r2), "=r"(r3) : "r"(addr));
}

__device__ __forceinline__ void mma_f16(float c[4], uint32_t a0, uint32_t a1, uint32_t a2,
                                        uint32_t a3, uint32_t b0, uint32_t b1) {
    asm volatile(
        "mma.sync.aligned.m16n8k16.row.col.f32.f16.f16.f32 "
        "{%0,%1,%2,%3}, {%4,%5,%6,%7}, {%8,%9}, {%0,%1,%2,%3};"
        : "+f"(c[0]), "+f"(c[1]), "+f"(c[2]), "+f"(c[3])
        : "r"(a0), "r"(a1), "r"(a2), "r"(a3), "r"(b0), "r"(b1));
}

__device__ __forceinline__ uint32_t pk2(float a, float b) {
    __half2 h = __floats2half2_rn(a, b);
    return *reinterpret_cast<uint32_t*>(&h);
}

// relu on packed half2: max.f16x2 with +0,+0
__device__ __forceinline__ uint32_t relu2(uint32_t p) {
    uint32_t r;
    asm("max.f16x2 %0, %1, %2;" : "=r"(r) : "r"(p), "r"(0u));
    return r;
}

__device__ __forceinline__ float2 lds_v2(uint32_t addr) {
    float2 v;
    asm volatile("ld.shared.v2.f32 {%0, %1}, [%2];" : "=f"(v.x), "=f"(v.y) : "r"(addr));
    return v;
}

__device__ __forceinline__ void red_add_v2(float* p, float a, float b) {
    asm volatile("red.global.add.v2.f32 [%0], {%1, %2};"
                 :: "l"(p), "f"(a), "f"(b) : "memory");
}

__device__ __forceinline__ void cp16(uint32_t dst, const void* src) {
    asm volatile("cp.async.cg.shared.global [%0], [%1], 16;" :: "r"(dst), "l"(src) : "memory");
}

// Issue the full gather for one tile as cp.async into the padded stage buffer.
__device__ __forceinline__ void issue_gather(uint32_t sb, const int* sSrc, const int* sTgt,
                                             const float* x, const float* efeat,
                                             long long base, int tid) {
    #pragma unroll
    for (int j = 0; j < 14; j++) {
        int f = j * 256 + tid;
        int row = f / 28;
        int q = f - row * 28;
        const float4* p;
        if (q < 12)      p = reinterpret_cast<const float4*>(x + (size_t)sSrc[row] * NFEAT) + q;
        else if (q < 24) p = reinterpret_cast<const float4*>(x + (size_t)sTgt[row] * NFEAT) + (q - 12);
        else             p = reinterpret_cast<const float4*>(efeat + (size_t)(base + row) * 16) + (q - 24);
        cp16(sb + SM_STAGE + row * SSTRIDE + q * 16, p);
    }
}

// ---------------- kernels ----------------

// zero scratch + detect edge_index width (int64 vs downcast int32; see R3 notes).
__global__ void zero_detect_kernel(const int* __restrict__ ei32) {
    if (blockIdx.x == 0 && threadIdx.x == 0) {
        int odd_or = 0;
        #pragma unroll 8
        for (int i = 0; i < 256; i++) odd_or |= ei32[2 * i + 1];
        g_stride = odd_or ? 1 : 2;
    }
    int n4 = NNODES * NFEAT / 4;
    float4 z = make_float4(0.f, 0.f, 0.f, 0.f);
    for (int i = blockIdx.x * blockDim.x + threadIdx.x; i < n4; i += gridDim.x * blockDim.x) {
        reinterpret_cast<float4*>(g_msum)[i] = z;
        if (i < NNODES) g_cnt[i] = 0.0f;
    }
}

__global__ void __launch_bounds__(256, 1)
gnn_fused_kernel(const float* __restrict__ x, const int* __restrict__ ei32,
                 const float* __restrict__ efeat,
                 const float* __restrict__ W1, const float* __restrict__ b1,
                 const float* __restrict__ W2, const float* __restrict__ b2,
                 const float* __restrict__ W3, const float* __restrict__ b3) {
    extern __shared__ char smem[];
    const uint32_t sb = smem_to_u32(smem);
    const int tid = threadIdx.x;
    const int w = tid >> 5;
    const int l = tid & 31;
    const long long stride = (long long)g_stride;

    // ---- one-time init: zero weight tiles (pad columns must be 0) ----
    for (int i = tid; i < (SM_STAGE - SM_W1) / 16; i += 256)
        reinterpret_cast<uint4*>(smem + SM_W1)[i] = make_uint4(0, 0, 0, 0);
    __syncthreads();

    // Weights transposed: Wt[n][k] = W[k][n], fp16, row stride ESTRIDE.
    for (int idx = tid; idx < 112 * HID; idx += 256) {
        int k = idx >> 7, n = idx & 127;
        *reinterpret_cast<__half*>(smem + SM_W1 + n * ESTRIDE + k * 2) = __float2half(W1[idx]);
    }
    for (int idx = tid; idx < HID * HID; idx += 256) {
        int k = idx >> 7, n = idx & 127;
        *reinterpret_cast<__half*>(smem + SM_W2 + n * ESTRIDE + k * 2) = __float2half(W2[idx]);
    }
    for (int idx = tid; idx < HID * NFEAT; idx += 256) {
        int k = idx / NFEAT, n = idx - k * NFEAT;
        *reinterpret_cast<__half*>(smem + SM_W3 + n * ESTRIDE + k * 2) = __float2half(W3[idx]);
    }
    if (tid < HID) {
        reinterpret_cast<float*>(smem + SM_B1)[tid] = b1[tid];
        reinterpret_cast<float*>(smem + SM_B2)[tid] = b2[tid];
    }
    if (tid < NFEAT) reinterpret_cast<float*>(smem + SM_B3)[tid] = b3[tid];
    __syncthreads();

    // ldmatrix B addressing (x4 over TWO n-tiles): g=l>>3: g0=t klo, g1=t khi, g2=t+1 klo, g3=t+1 khi
    const uint32_t woff4 = (uint32_t)(l & 7) * ESTRIDE + (((l >> 3) & 1) << 4)
                         + (uint32_t)(l >> 4) * (8 * ESTRIDE);
    const uint32_t wb1 = sb + SM_W1 + woff4;
    const uint32_t wb2 = sb + SM_W2 + woff4;
    const uint32_t wb3 = sb + SM_W3 + woff4;

    // A-fragment stage addressing: lane reads its own m16n8k16 coords.
    // rows r0 = 16w + (l>>2), r0+8 ; cols j*16 + (l&3)*2 (+8)
    const int cb = 2 * (l & 3);
    const uint32_t stA = sb + SM_STAGE + (uint32_t)(16 * w + (l >> 2)) * SSTRIDE + (uint32_t)cb * 4;
    // bias init addresses (c0/c1 cols = 8t + cb)
    const uint32_t b1a = sb + SM_B1 + (uint32_t)cb * 4;
    const uint32_t b2a = sb + SM_B2 + (uint32_t)cb * 4;
    const uint32_t b3a = sb + SM_B3 + (uint32_t)cb * 4;

    // ---- prologue: indices + gather for first tile ----
    int cur = 0;
    {
        long long e = (long long)blockIdx.x * 128 + tid;
        if (tid < 128) {
            int s = ei32[stride * e];
            int t = ei32[stride * (NEDGES + e)];
            reinterpret_cast<int*>(smem + SM_SRC0)[tid] = min(max(s, 0), NNODES - 1);
            reinterpret_cast<int*>(smem + SM_TGT0)[tid] = min(max(t, 0), NNODES - 1);
        }
        __syncthreads();
        issue_gather(sb, reinterpret_cast<const int*>(smem + SM_SRC0),
                     reinterpret_cast<const int*>(smem + SM_TGT0),
                     x, efeat, (long long)blockIdx.x * 128, tid);
        asm volatile("cp.async.commit_group;" ::: "memory");
    }

    for (int tile = blockIdx.x; tile < NTILES; tile += gridDim.x) {
        const int next = tile + gridDim.x;
        const int* sTgtC = reinterpret_cast<const int*>(smem + (cur ? SM_TGT1 : SM_TGT0));
        int* sSrcN = reinterpret_cast<int*>(smem + (cur ? SM_SRC0 : SM_SRC1));
        int* sTgtN = reinterpret_cast<int*>(smem + (cur ? SM_TGT0 : SM_TGT1));

        // ---- stage ready ----
        asm volatile("cp.async.wait_group 0;" ::: "memory");
        __syncthreads();

        // ---- prefetch next tile's indices under layer 1 ----
        int nsrc = 0, ntgt = 0;
        if (next < NTILES && tid < 128) {
            long long e = (long long)next * 128 + tid;
            nsrc = ei32[stride * e];
            ntgt = ei32[stride * (NEDGES + e)];
        }

        // ---- Layer 1: h1 = relu(E @ W1^T + b1); A-frags read directly from stage ----
        float a1[16][4];
        #pragma unroll
        for (int t = 0; t < 16; t++) {
            float2 bv = lds_v2(b1a + t * 32);
            a1[t][0] = bv.x; a1[t][1] = bv.y; a1[t][2] = bv.x; a1[t][3] = bv.y;
        }
        #pragma unroll
        for (int j = 0; j < 7; j++) {          // K = 112 exactly: 7 k-steps
            float2 v00 = lds_v2(stA + j * 64);
            float2 v10 = lds_v2(stA + 8 * SSTRIDE + j * 64);
            float2 v01 = lds_v2(stA + 32 + j * 64);
            float2 v11 = lds_v2(stA + 8 * SSTRIDE + 32 + j * 64);
            uint32_t A0 = pk2(v00.x, v00.y), A1 = pk2(v10.x, v10.y);
            uint32_t A2 = pk2(v01.x, v01.y), A3 = pk2(v11.x, v11.y);
            #pragma unroll
            for (int t = 0; t < 16; t += 2) {
                uint32_t B0, B1, B2, B3;
                ldsm_x4(B0, B1, B2, B3, wb1 + (uint32_t)t * (8 * ESTRIDE) + 32 * j);
                mma_f16(a1[t],     A0, A1, A2, A3, B0, B1);
                mma_f16(a1[t + 1], A0, A1, A2, A3, B2, B3);
            }
        }
        uint32_t h1[32];
        #pragma unroll
        for (int t = 0; t < 16; t++) {
            h1[2 * t]     = relu2(pk2(a1[t][0], a1[t][1]));
            h1[2 * t + 1] = relu2(pk2(a1[t][2], a1[t][3]));
        }

        // ---- store next indices, sync (stage free), kick off next gather ----
        if (next < NTILES && tid < 128) {
            sSrcN[tid] = min(max(nsrc, 0), NNODES - 1);
            sTgtN[tid] = min(max(ntgt, 0), NNODES - 1);
        }
        __syncthreads();
        if (next < NTILES)
            issue_gather(sb, sSrcN, sTgtN, x, efeat, (long long)next * 128, tid);
        asm volatile("cp.async.commit_group;" ::: "memory");

        // ---- Layer 2: h2 = relu(h1 @ W2^T + b2) ----
        float a2[16][4];
        #pragma unroll
        for (int t = 0; t < 16; t++) {
            float2 bv = lds_v2(b2a + t * 32);
            a2[t][0] = bv.x; a2[t][1] = bv.y; a2[t][2] = bv.x; a2[t][3] = bv.y;
        }
        #pragma unroll
        for (int j = 0; j < 8; j++) {
            #pragma unroll
            for (int t = 0; t < 16; t += 2) {
                uint32_t B0, B1, B2, B3;
                ldsm_x4(B0, B1, B2, B3, wb2 + (uint32_t)t * (8 * ESTRIDE) + 32 * j);
                mma_f16(a2[t],     h1[4 * j], h1[4 * j + 1], h1[4 * j + 2], h1[4 * j + 3], B0, B1);
                mma_f16(a2[t + 1], h1[4 * j], h1[4 * j + 1], h1[4 * j + 2], h1[4 * j + 3], B2, B3);
            }
        }
        uint32_t h2[32];
        #pragma unroll
        for (int t = 0; t < 16; t++) {
            h2[2 * t]     = relu2(pk2(a2[t][0], a2[t][1]));
            h2[2 * t + 1] = relu2(pk2(a2[t][2], a2[t][3]));
        }

        // ---- Layer 3: msg = h2 @ W3^T + b3 (N = 48) ----
        float a3[6][4];
        #pragma unroll
        for (int t = 0; t < 6; t++) {
            float2 bv = lds_v2(b3a + t * 32);
            a3[t][0] = bv.x; a3[t][1] = bv.y; a3[t][2] = bv.x; a3[t][3] = bv.y;
        }
        #pragma unroll
        for (int j = 0; j < 8; j++) {
            #pragma unroll
            for (int t = 0; t < 6; t += 2) {
                uint32_t B0, B1, B2, B3;
                ldsm_x4(B0, B1, B2, B3, wb3 + (uint32_t)t * (8 * ESTRIDE) + 32 * j);
                mma_f16(a3[t],     h2[4 * j], h2[4 * j + 1], h2[4 * j + 2], h2[4 * j + 3], B0, B1);
                mma_f16(a3[t + 1], h2[4 * j], h2[4 * j + 1], h2[4 * j + 2], h2[4 * j + 3], B2, B3);
            }
        }

        // ---- direct register scatter: rows r0=(16w + l>>2), r1=r0+8 ----
        {
            int r0 = 16 * w + (l >> 2), r1 = r0 + 8;
            int tgt0 = sTgtC[r0], tgt1 = sTgtC[r1];
            float* d0 = g_msum + (size_t)tgt0 * NFEAT + cb;
            float* d1 = g_msum + (size_t)tgt1 * NFEAT + cb;
            #pragma unroll
            for (int t = 0; t < 6; t++) {
                red_add_v2(d0 + 8 * t, a3[t][0], a3[t][1]);
                red_add_v2(d1 + 8 * t, a3[t][2], a3[t][3]);
            }
            if ((l & 3) == 0) {
                asm volatile("red.global.add.f32 [%0], %1;" :: "l"(g_cnt + tgt0), "f"(1.0f) : "memory");
                asm volatile("red.global.add.f32 [%0], %1;" :: "l"(g_cnt + tgt1), "f"(1.0f) : "memory");
            }
        }
        cur ^= 1;
    }
}

__global__ void finalize_kernel(const float* __restrict__ x, float* __restrict__ out) {
    int i = blockIdx.x * blockDim.x + threadIdx.x;
    int n4 = NNODES * NFEAT / 4;
    if (i < n4) {
        int node = i / 12;   // 12 float4 per node (48 feats)
        float inv = __fdividef(1.0f, fmaxf(g_cnt[node], 1.0f));
        float4 m = reinterpret_cast<const float4*>(g_msum)[i];
        float4 xv = reinterpret_cast<const float4*>(x)[i];
        float4 o;
        o.x = xv.x + m.x * inv;
        o.y = xv.y + m.y * inv;
        o.z = xv.z + m.z * inv;
        o.w = xv.w + m.w * inv;
        reinterpret_cast<float4*>(out)[i] = o;
    }
}

// ---------------- launch ----------------
extern "C" void kernel_launch(void* const* d_in, const int* in_sizes, int n_in,
                              void* d_out, int out_size) {
    const float* x  = (const float*)d_in[0];
    const int*   ei = (const int*)d_in[1];
    const float* ef = (const float*)d_in[2];
    const float* W1 = (const float*)d_in[3];
    const float* b1 = (const float*)d_in[4];
    const float* W2 = (const float*)d_in[5];
    const float* b2 = (const float*)d_in[6];
    const float* W3 = (const float*)d_in[7];
    const float* b3 = (const float*)d_in[8];

    cudaFuncSetAttribute(gnn_fused_kernel,
                         cudaFuncAttributeMaxDynamicSharedMemorySize, SMEM_TOTAL);

    zero_detect_kernel<<<1024, 256>>>(ei);
    gnn_fused_kernel<<<148, 256, SMEM_TOTAL>>>(x, ei, ef, W1, b1, W2, b2, W3, b3);
    finalize_kernel<<<(NNODES * NFEAT / 4 + 255) / 256, 256>>>(x, (float*)d_out);
}

// round 9
// speedup vs baseline: 2.1291x; 1.0295x over previous
#include <cuda_runtime.h>
#include <cuda_fp16.h>
#include <cstdint>

#define NNODES 100000
#define NEDGES 1600000
#define NFEAT 48
#define HID 128
#define NTILES (NEDGES / 128)   // 12500 exactly

// Scratch (no allocation allowed): 19.2MB msum + 400KB cnt
__device__ float g_msum[(size_t)NNODES * NFEAT];
__device__ float g_cnt[NNODES];
__device__ int g_stride;   // edge_index word stride: 2 = int64 storage, 1 = int32

// ---------------- SMEM layout (bytes) ----------------
#define ESTRIDE 272               // weight rows: 128 fp16 cols padded +16B (conflict-free ldsm)
#define SSTRIDE 464               // stage rows: 112 f32 + 4 pad floats (16B-aligned, bank-spread)
#define SM_SRC0 0                 // 128 x int32
#define SM_TGT0 512
#define SM_SRC1 1024
#define SM_TGT1 1536
#define SM_HB1  2048              // 64 x half2 packed bias b1 (256B)
#define SM_HB2  2304              // 64 x half2 packed bias b2 (256B)
#define SM_B3   2560              // 48 x f32 (256B slot)
#define SM_W1   2816                       // 128 rows
#define SM_W2   (SM_W1 + 128 * ESTRIDE)    // 37632
#define SM_W3   (SM_W2 + 128 * ESTRIDE)    // 72448 (48 rows)
#define SM_STAGE (SM_W3 + 48 * ESTRIDE)    // 85504, fp32 gather stage 128 x SSTRIDE
#define SMEM_TOTAL (SM_STAGE + 128 * SSTRIDE)   // 144896 bytes

// ---------------- helpers ----------------
__device__ __forceinline__ uint32_t smem_to_u32(const void* p) {
    uint32_t a;
    asm("{ .reg .u64 t; cvta.to.shared.u64 t, %1; cvt.u32.u64 %0, t; }" : "=r"(a) : "l"(p));
    return a;
}

__device__ __forceinline__ void ldsm_x4(uint32_t& r0, uint32_t& r1, uint32_t& r2, uint32_t& r3,
                                        uint32_t addr) {
    asm volatile("ldmatrix.sync.aligned.m8n8.x4.shared.b16 {%0,%1,%2,%3}, [%4];"
                 : "=r"(r0), "=r"(r1), "=r"(r2), "=r"(r3) : "r"(addr));
}

// f32-accumulator MMA (layer 3)
__device__ __forceinline__ void mma_f16(float c[4], uint32_t a0, uint32_t a1, uint32_t a2,
                                        uint32_t a3, uint32_t b0, uint32_t b1) {
    asm volatile(
        "mma.sync.aligned.m16n8k16.row.col.f32.f16.f16.f32 "
        "{%0,%1,%2,%3}, {%4,%5,%6,%7}, {%8,%9}, {%0,%1,%2,%3};"
        : "+f"(c[0]), "+f"(c[1]), "+f"(c[2]), "+f"(c[3])
        : "r"(a0), "r"(a1), "r"(a2), "r"(a3), "r"(b0), "r"(b1));
}

// f16-accumulator MMA (layers 1-2): C regs are packed half2, same coords as A-frags
__device__ __forceinline__ void mma_f16acc(uint32_t c[2], uint32_t a0, uint32_t a1, uint32_t a2,
                                           uint32_t a3, uint32_t b0, uint32_t b1) {
    asm volatile(
        "mma.sync.aligned.m16n8k16.row.col.f16.f16.f16.f16 "
        "{%0,%1}, {%2,%3,%4,%5}, {%6,%7}, {%0,%1};"
        : "+r"(c[0]), "+r"(c[1])
        : "r"(a0), "r"(a1), "r"(a2), "r"(a3), "r"(b0), "r"(b1));
}

__device__ __forceinline__ uint32_t pk2(float a, float b) {
    __half2 h = __floats2half2_rn(a, b);
    return *reinterpret_cast<uint32_t*>(&h);
}

// relu on packed half2: max.f16x2 with +0,+0
__device__ __forceinline__ uint32_t relu2(uint32_t p) {
    uint32_t r;
    asm("max.f16x2 %0, %1, %2;" : "=r"(r) : "r"(p), "r"(0u));
    return r;
}

__device__ __forceinline__ float2 lds_v2(uint32_t addr) {
    float2 v;
    asm volatile("ld.shared.v2.f32 {%0, %1}, [%2];" : "=f"(v.x), "=f"(v.y) : "r"(addr));
    return v;
}

__device__ __forceinline__ uint32_t lds_b32(uint32_t addr) {
    uint32_t v;
    asm volatile("ld.shared.b32 %0, [%1];" : "=r"(v) : "r"(addr));
    return v;
}

__device__ __forceinline__ void red_add_v2(float* p, float a, float b) {
    asm volatile("red.global.add.v2.f32 [%0], {%1, %2};"
                 :: "l"(p), "f"(a), "f"(b) : "memory");
}

__device__ __forceinline__ void cp16(uint32_t dst, const void* src) {
    asm volatile("cp.async.cg.shared.global [%0], [%1], 16;" :: "r"(dst), "l"(src) : "memory");
}

// Issue the full gather for one tile as cp.async into the padded stage buffer.
__device__ __forceinline__ void issue_gather(uint32_t sb, const int* sSrc, const int* sTgt,
                                             const float* x, const float* efeat,
                                             long long base, int tid) {
    #pragma unroll
    for (int j = 0; j < 14; j++) {
        int f = j * 256 + tid;
        int row = f / 28;
        int q = f - row * 28;
        const float4* p;
        if (q < 12)      p = reinterpret_cast<const float4*>(x + (size_t)sSrc[row] * NFEAT) + q;
        else if (q < 24) p = reinterpret_cast<const float4*>(x + (size_t)sTgt[row] * NFEAT) + (q - 12);
        else             p = reinterpret_cast<const float4*>(efeat + (size_t)(base + row) * 16) + (q - 24);
        cp16(sb + SM_STAGE + row * SSTRIDE + q * 16, p);
    }
}

// ---------------- kernels ----------------

// zero scratch + detect edge_index width (int64 vs downcast int32; see R3 notes).
__global__ void zero_detect_kernel(const int* __restrict__ ei32) {
    if (blockIdx.x == 0 && threadIdx.x == 0) {
        int odd_or = 0;
        #pragma unroll 8
        for (int i = 0; i < 256; i++) odd_or |= ei32[2 * i + 1];
        g_stride = odd_or ? 1 : 2;
    }
    int n4 = NNODES * NFEAT / 4;
    float4 z = make_float4(0.f, 0.f, 0.f, 0.f);
    for (int i = blockIdx.x * blockDim.x + threadIdx.x; i < n4; i += gridDim.x * blockDim.x) {
        reinterpret_cast<float4*>(g_msum)[i] = z;
        if (i < NNODES) g_cnt[i] = 0.0f;
    }
}

__global__ void __launch_bounds__(256, 1)
gnn_fused_kernel(const float* __restrict__ x, const int* __restrict__ ei32,
                 const float* __restrict__ efeat,
                 const float* __restrict__ W1, const float* __restrict__ b1,
                 const float* __restrict__ W2, const float* __restrict__ b2,
                 const float* __restrict__ W3, const float* __restrict__ b3) {
    extern __shared__ char smem[];
    const uint32_t sb = smem_to_u32(smem);
    const int tid = threadIdx.x;
    const int w = tid >> 5;
    const int l = tid & 31;
    const long long stride = (long long)g_stride;

    // ---- one-time init: zero weight tiles (pad columns must be 0) ----
    for (int i = tid; i < (SM_STAGE - SM_W1) / 16; i += 256)
        reinterpret_cast<uint4*>(smem + SM_W1)[i] = make_uint4(0, 0, 0, 0);
    __syncthreads();

    // Weights transposed: Wt[n][k] = W[k][n], fp16, row stride ESTRIDE.
    for (int idx = tid; idx < 112 * HID; idx += 256) {
        int k = idx >> 7, n = idx & 127;
        *reinterpret_cast<__half*>(smem + SM_W1 + n * ESTRIDE + k * 2) = __float2half(W1[idx]);
    }
    for (int idx = tid; idx < HID * HID; idx += 256) {
        int k = idx >> 7, n = idx & 127;
        *reinterpret_cast<__half*>(smem + SM_W2 + n * ESTRIDE + k * 2) = __float2half(W2[idx]);
    }
    for (int idx = tid; idx < HID * NFEAT; idx += 256) {
        int k = idx / NFEAT, n = idx - k * NFEAT;
        *reinterpret_cast<__half*>(smem + SM_W3 + n * ESTRIDE + k * 2) = __float2half(W3[idx]);
    }
    if (tid < 64) {
        reinterpret_cast<__half2*>(smem + SM_HB1)[tid] =
            __floats2half2_rn(b1[2 * tid], b1[2 * tid + 1]);
        reinterpret_cast<__half2*>(smem + SM_HB2)[tid] =
            __floats2half2_rn(b2[2 * tid], b2[2 * tid + 1]);
    }
    if (tid < NFEAT) reinterpret_cast<float*>(smem + SM_B3)[tid] = b3[tid];
    __syncthreads();

    // ldmatrix B addressing (x4 over TWO n-tiles): g=l>>3: g0=t klo, g1=t khi, g2=t+1 klo, g3=t+1 khi
    const uint32_t woff4 = (uint32_t)(l & 7) * ESTRIDE + (((l >> 3) & 1) << 4)
                         + (uint32_t)(l >> 4) * (8 * ESTRIDE);
    const uint32_t wb1 = sb + SM_W1 + woff4;
    const uint32_t wb2 = sb + SM_W2 + woff4;
    const uint32_t wb3 = sb + SM_W3 + woff4;

    // A-fragment stage addressing: lane reads its own m16n8k16 coords.
    // rows r0 = 16w + (l>>2), r0+8 ; cols j*16 + (l&3)*2 (+8)
    const int cb = 2 * (l & 3);
    const uint32_t stA = sb + SM_STAGE + (uint32_t)(16 * w + (l >> 2)) * SSTRIDE + (uint32_t)cb * 4;
    // bias addresses: packed half2 at index 4t + (l&3); layer-3 f32 pair at 8t + cb
    const uint32_t hb1a = sb + SM_HB1 + (uint32_t)(l & 3) * 4;
    const uint32_t hb2a = sb + SM_HB2 + (uint32_t)(l & 3) * 4;
    const uint32_t b3a = sb + SM_B3 + (uint32_t)cb * 4;

    // ---- prologue: indices + gather for first tile ----
    int cur = 0;
    {
        long long e = (long long)blockIdx.x * 128 + tid;
        if (tid < 128) {
            int s = ei32[stride * e];
            int t = ei32[stride * (NEDGES + e)];
            reinterpret_cast<int*>(smem + SM_SRC0)[tid] = min(max(s, 0), NNODES - 1);
            reinterpret_cast<int*>(smem + SM_TGT0)[tid] = min(max(t, 0), NNODES - 1);
        }
        __syncthreads();
        issue_gather(sb, reinterpret_cast<const int*>(smem + SM_SRC0),
                     reinterpret_cast<const int*>(smem + SM_TGT0),
                     x, efeat, (long long)blockIdx.x * 128, tid);
        asm volatile("cp.async.commit_group;" ::: "memory");
    }

    for (int tile = blockIdx.x; tile < NTILES; tile += gridDim.x) {
        const int next = tile + gridDim.x;
        const int* sTgtC = reinterpret_cast<const int*>(smem + (cur ? SM_TGT1 : SM_TGT0));
        int* sSrcN = reinterpret_cast<int*>(smem + (cur ? SM_SRC0 : SM_SRC1));
        int* sTgtN = reinterpret_cast<int*>(smem + (cur ? SM_TGT0 : SM_TGT1));

        // ---- stage ready ----
        asm volatile("cp.async.wait_group 0;" ::: "memory");
        __syncthreads();

        // ---- prefetch next tile's indices under layer 1 ----
        int nsrc = 0, ntgt = 0;
        if (next < NTILES && tid < 128) {
            long long e = (long long)next * 128 + tid;
            nsrc = ei32[stride * e];
            ntgt = ei32[stride * (NEDGES + e)];
        }

        // ---- Layer 1: h1 = relu(E @ W1^T + b1); f16 accumulators ----
        uint32_t a1[16][2];
        #pragma unroll
        for (int t = 0; t < 16; t++) {
            uint32_t hb = lds_b32(hb1a + t * 16);
            a1[t][0] = hb; a1[t][1] = hb;
        }
        #pragma unroll
        for (int j = 0; j < 7; j++) {          // K = 112 exactly: 7 k-steps
            float2 v00 = lds_v2(stA + j * 64);
            float2 v10 = lds_v2(stA + 8 * SSTRIDE + j * 64);
            float2 v01 = lds_v2(stA + 32 + j * 64);
            float2 v11 = lds_v2(stA + 8 * SSTRIDE + 32 + j * 64);
            uint32_t A0 = pk2(v00.x, v00.y), A1 = pk2(v10.x, v10.y);
            uint32_t A2 = pk2(v01.x, v01.y), A3 = pk2(v11.x, v11.y);
            #pragma unroll
            for (int t = 0; t < 16; t += 2) {
                uint32_t B0, B1, B2, B3;
                ldsm_x4(B0, B1, B2, B3, wb1 + (uint32_t)t * (8 * ESTRIDE) + 32 * j);
                mma_f16acc(a1[t],     A0, A1, A2, A3, B0, B1);
                mma_f16acc(a1[t + 1], A0, A1, A2, A3, B2, B3);
            }
        }
        uint32_t h1[32];
        #pragma unroll
        for (int t = 0; t < 16; t++) {
            h1[2 * t]     = relu2(a1[t][0]);
            h1[2 * t + 1] = relu2(a1[t][1]);
        }

        // ---- store next indices, sync (stage free), kick off next gather ----
        if (next < NTILES && tid < 128) {
            sSrcN[tid] = min(max(nsrc, 0), NNODES - 1);
            sTgtN[tid] = min(max(ntgt, 0), NNODES - 1);
        }
        __syncthreads();
        if (next < NTILES)
            issue_gather(sb, sSrcN, sTgtN, x, efeat, (long long)next * 128, tid);
        asm volatile("cp.async.commit_group;" ::: "memory");

        // ---- Layer 2: h2 = relu(h1 @ W2^T + b2); f16 accumulators ----
        uint32_t a2[16][2];
        #pragma unroll
        for (int t = 0; t < 16; t++) {
            uint32_t hb = lds_b32(hb2a + t * 16);
            a2[t][0] = hb; a2[t][1] = hb;
        }
        #pragma unroll
        for (int j = 0; j < 8; j++) {
            #pragma unroll
            for (int t = 0; t < 16; t += 2) {
                uint32_t B0, B1, B2, B3;
                ldsm_x4(B0, B1, B2, B3, wb2 + (uint32_t)t * (8 * ESTRIDE) + 32 * j);
                mma_f16acc(a2[t],     h1[4 * j], h1[4 * j + 1], h1[4 * j + 2], h1[4 * j + 3], B0, B1);
                mma_f16acc(a2[t + 1], h1[4 * j], h1[4 * j + 1], h1[4 * j + 2], h1[4 * j + 3], B2, B3);
            }
        }
        uint32_t h2[32];
        #pragma unroll
        for (int t = 0; t < 16; t++) {
            h2[2 * t]     = relu2(a2[t][0]);
            h2[2 * t + 1] = relu2(a2[t][1]);
        }

        // ---- Layer 3: msg = h2 @ W3^T + b3 (N = 48); f32 accumulators ----
        float a3[6][4];
        #pragma unroll
        for (int t = 0; t < 6; t++) {
            float2 bv = lds_v2(b3a + t * 32);
            a3[t][0] = bv.x; a3[t][1] = bv.y; a3[t][2] = bv.x; a3[t][3] = bv.y;
        }
        #pragma unroll
        for (int j = 0; j < 8; j++) {
            #pragma unroll
            for (int t = 0; t < 6; t += 2) {
                uint32_t B0, B1, B2, B3;
                ldsm_x4(B0, B1, B2, B3, wb3 + (uint32_t)t * (8 * ESTRIDE) + 32 * j);
                mma_f16(a3[t],     h2[4 * j], h2[4 * j + 1], h2[4 * j + 2], h2[4 * j + 3], B0, B1);
                mma_f16(a3[t + 1], h2[4 * j], h2[4 * j + 1], h2[4 * j + 2], h2[4 * j + 3], B2, B3);
            }
        }

        // ---- direct register scatter: rows r0=(16w + l>>2), r1=r0+8 ----
        {
            int r0 = 16 * w + (l >> 2), r1 = r0 + 8;
            int tgt0 = sTgtC[r0], tgt1 = sTgtC[r1];
            float* d0 = g_msum + (size_t)tgt0 * NFEAT + cb;
            float* d1 = g_msum + (size_t)tgt1 * NFEAT + cb;
            #pragma unroll
            for (int t = 0; t < 6; t++) {
                red_add_v2(d0 + 8 * t, a3[t][0], a3[t][1]);
                red_add_v2(d1 + 8 * t, a3[t][2], a3[t][3]);
            }
            if ((l & 3) == 0) {
                asm volatile("red.global.add.f32 [%0], %1;" :: "l"(g_cnt + tgt0), "f"(1.0f) : "memory");
                asm volatile("red.global.add.f32 [%0], %1;" :: "l"(g_cnt + tgt1), "f"(1.0f) : "memory");
            }
        }
        cur ^= 1;
    }
}

__global__ void finalize_kernel(const float* __restrict__ x, float* __restrict__ out) {
    int i = blockIdx.x * blockDim.x + threadIdx.x;
    int n4 = NNODES * NFEAT / 4;
    if (i < n4) {
        int node = i / 12;   // 12 float4 per node (48 feats)
        float inv = __fdividef(1.0f, fmaxf(g_cnt[node], 1.0f));
        float4 m = reinterpret_cast<const float4*>(g_msum)[i];
        float4 xv = reinterpret_cast<const float4*>(x)[i];
        float4 o;
        o.x = xv.x + m.x * inv;
        o.y = xv.y + m.y * inv;
        o.z = xv.z + m.z * inv;
        o.w = xv.w + m.w * inv;
        reinterpret_cast<float4*>(out)[i] = o;
    }
}

// ---------------- launch ----------------
extern "C" void kernel_launch(void* const* d_in, const int* in_sizes, int n_in,
                              void* d_out, int out_size) {
    const float* x  = (const float*)d_in[0];
    const int*   ei = (const int*)d_in[1];
    const float* ef = (const float*)d_in[2];
    const float* W1 = (const float*)d_in[3];
    const float* b1 = (const float*)d_in[4];
    const float* W2 = (const float*)d_in[5];
    const float* b2 = (const float*)d_in[6];
    const float* W3 = (const float*)d_in[7];
    const float* b3 = (const float*)d_in[8];

    cudaFuncSetAttribute(gnn_fused_kernel,
                         cudaFuncAttributeMaxDynamicSharedMemorySize, SMEM_TOTAL);

    zero_detect_kernel<<<1024, 256>>>(ei);
    gnn_fused_kernel<<<148, 256, SMEM_TOTAL>>>(x, ei, ef, W1, b1, W2, b2, W3, b3);
    finalize_kernel<<<(NNODES * NFEAT / 4 + 255) / 256, 256>>>(x, (float*)d_out);
}

// round 10
// speedup vs baseline: 2.2195x; 1.0425x over previous
#include <cuda_runtime.h>
#include <cuda_fp16.h>
#include <cstdint>

#define NNODES 100000
#define NEDGES 1600000
#define NFEAT 48
#define HID 128
#define NTILES (NEDGES / 128)   // 12500 exactly

// Scratch (no allocation allowed)
__device__ float g_msum[(size_t)NNODES * NFEAT];          // 19.2MB
__device__ float g_cnt[NNODES];
__device__ int g_stride;   // edge_index word stride: 2 = int64 storage, 1 = int32
__device__ __align__(16) __half g_PQ[(size_t)NNODES * 256];  // 51.2MB: per node [P(128h) | Q(128h)]

// ---------------- SMEM layout (bytes), main kernel ----------------
#define ESTRIDE 272               // W2/W3 rows: 128 fp16 padded +16B (conflict-free ldsm)
#define WCSTRIDE 48               // W1c rows: 16 fp16 (32B) padded to 48B
#define SSTRIDE 592               // stage row: P 256B | Q 256B | ef 64B | pad 16B
#define SM_SRC0 0                 // 128 x int32
#define SM_TGT0 512
#define SM_SRC1 1024
#define SM_TGT1 1536
#define SM_HB1  2048              // 64 x half2 packed bias b1 (256B)
#define SM_HB2  2304              // 64 x half2 packed bias b2 (256B)
#define SM_B3   2560              // 48 x f32 (256B slot)
#define SM_W1C  2816                        // 128 rows x WCSTRIDE = 6144
#define SM_W2   (SM_W1C + 128 * WCSTRIDE)   // 8960
#define SM_W3   (SM_W2 + 128 * ESTRIDE)     // 43776 (48 rows)
#define SM_STAGE (SM_W3 + 48 * ESTRIDE)     // 56832
#define SMEM_TOTAL (SM_STAGE + 128 * SSTRIDE)   // 132608 bytes

// ---------------- helpers ----------------
__device__ __forceinline__ uint32_t smem_to_u32(const void* p) {
    uint32_t a;
    asm("{ .reg .u64 t; cvta.to.shared.u64 t, %1; cvt.u32.u64 %0, t; }" : "=r"(a) : "l"(p));
    return a;
}

__device__ __forceinline__ void ldsm_x4(uint32_t& r0, uint32_t& r1, uint32_t& r2, uint32_t& r3,
                                        uint32_t addr) {
    asm volatile("ldmatrix.sync.aligned.m8n8.x4.shared.b16 {%0,%1,%2,%3}, [%4];"
                 : "=r"(r0), "=r"(r1), "=r"(r2), "=r"(r3) : "r"(addr));
}

// f32-accumulator MMA (layer 3)
__device__ __forceinline__ void mma_f16(float c[4], uint32_t a0, uint32_t a1, uint32_t a2,
                                        uint32_t a3, uint32_t b0, uint32_t b1) {
    asm volatile(
        "mma.sync.aligned.m16n8k16.row.col.f32.f16.f16.f32 "
        "{%0,%1,%2,%3}, {%4,%5,%6,%7}, {%8,%9}, {%0,%1,%2,%3};"
        : "+f"(c[0]), "+f"(c[1]), "+f"(c[2]), "+f"(c[3])
        : "r"(a0), "r"(a1), "r"(a2), "r"(a3), "r"(b0), "r"(b1));
}

// f16-accumulator MMA: C regs are packed half2, same coords as A-frags
__device__ __forceinline__ void mma_f16acc(uint32_t c[2], uint32_t a0, uint32_t a1, uint32_t a2,
                                           uint32_t a3, uint32_t b0, uint32_t b1) {
    asm volatile(
        "mma.sync.aligned.m16n8k16.row.col.f16.f16.f16.f16 "
        "{%0,%1}, {%2,%3,%4,%5}, {%6,%7}, {%0,%1};"
        : "+r"(c[0]), "+r"(c[1])
        : "r"(a0), "r"(a1), "r"(a2), "r"(a3), "r"(b0), "r"(b1));
}

__device__ __forceinline__ uint32_t pk2(float a, float b) {
    __half2 h = __floats2half2_rn(a, b);
    return *reinterpret_cast<uint32_t*>(&h);
}

__device__ __forceinline__ uint32_t relu2(uint32_t p) {
    uint32_t r;
    asm("max.f16x2 %0, %1, %2;" : "=r"(r) : "r"(p), "r"(0u));
    return r;
}

__device__ __forceinline__ uint32_t hadd2u(uint32_t a, uint32_t b) {
    uint32_t r;
    asm("add.f16x2 %0, %1, %2;" : "=r"(r) : "r"(a), "r"(b));
    return r;
}

__device__ __forceinline__ float2 lds_v2(uint32_t addr) {
    float2 v;
    asm volatile("ld.shared.v2.f32 {%0, %1}, [%2];" : "=f"(v.x), "=f"(v.y) : "r"(addr));
    return v;
}

__device__ __forceinline__ uint32_t lds_b32(uint32_t addr) {
    uint32_t v;
    asm volatile("ld.shared.b32 %0, [%1];" : "=r"(v) : "r"(addr));
    return v;
}

__device__ __forceinline__ void red_add_v2(float* p, float a, float b) {
    asm volatile("red.global.add.v2.f32 [%0], {%1, %2};"
                 :: "l"(p), "f"(a), "f"(b) : "memory");
}

__device__ __forceinline__ void cp16(uint32_t dst, const void* src) {
    asm volatile("cp.async.cg.shared.global [%0], [%1], 16;" :: "r"(dst), "l"(src) : "memory");
}

// Gather one tile: P[src] (16x16B) | Q[tgt] (16x16B) | ef (4x16B) per row, contiguous in stage.
__device__ __forceinline__ void issue_gather(uint32_t sb, const int* sSrc, const int* sTgt,
                                             const float* efeat, long long base, int tid) {
    const char* pqb = reinterpret_cast<const char*>(g_PQ);
    #pragma unroll
    for (int j = 0; j < 18; j++) {           // 128 rows * 36 chunks / 256 threads
        int f = j * 256 + tid;
        int row = f / 36;
        int q = f - row * 36;
        const void* src;
        if (q < 32) {
            int node = (q < 16) ? sSrc[row] : sTgt[row];
            src = pqb + (size_t)node * 512 + q * 16;    // Q section starts at byte 256 = 16*16
        } else {
            src = reinterpret_cast<const char*>(efeat) + (size_t)(base + row) * 64 + (q - 32) * 16;
        }
        cp16(sb + SM_STAGE + row * SSTRIDE + q * 16, src);
    }
}

// ---------------- kernels ----------------

// zero scratch + detect edge_index width (int64 vs downcast int32; see R3 notes).
__global__ void zero_detect_kernel(const int* __restrict__ ei32) {
    if (blockIdx.x == 0 && threadIdx.x == 0) {
        int odd_or = 0;
        #pragma unroll 8
        for (int i = 0; i < 256; i++) odd_or |= ei32[2 * i + 1];
        g_stride = odd_or ? 1 : 2;
    }
    int n4 = NNODES * NFEAT / 4;
    float4 z = make_float4(0.f, 0.f, 0.f, 0.f);
    for (int i = blockIdx.x * blockDim.x + threadIdx.x; i < n4; i += gridDim.x * blockDim.x) {
        reinterpret_cast<float4*>(g_msum)[i] = z;
        if (i < NNODES) g_cnt[i] = 0.0f;
    }
}

// Precompute PQ[n] = [ x[n] @ W1[0:48] , x[n] @ W1[48:96] ]  (fp16, f16 accum)
__global__ void __launch_bounds__(256, 1)
precompute_kernel(const float* __restrict__ x, const float* __restrict__ W1) {
    __shared__ __align__(16) char smw[256 * 112];   // Wt: 256 n-rows x 48 k fp16, stride 112B
    const int tid = threadIdx.x;
    const int w = tid >> 5;
    const int l = tid & 31;

    for (int idx = tid; idx < 256 * 48; idx += 256) {
        int n = idx / 48, k = idx - n * 48;
        float v = (n < 128) ? W1[k * HID + n] : W1[(48 + k) * HID + (n - 128)];
        *reinterpret_cast<__half*>(smw + n * 112 + k * 2) = __float2half(v);
    }
    __syncthreads();

    const uint32_t sbw = smem_to_u32(smw);
    const uint32_t wbp = sbw + (uint32_t)(l & 7) * 112 + (((l >> 3) & 1) << 4)
                       + (uint32_t)(l >> 4) * (8 * 112);
    const int cb = 2 * (l & 3);
    int r0 = blockIdx.x * 128 + 16 * w + (l >> 2);
    int r1 = r0 + 8;
    int r0c = min(r0, NNODES - 1), r1c = min(r1, NNODES - 1);
    const float* x0 = x + (size_t)r0c * NFEAT;
    const float* x1 = x + (size_t)r1c * NFEAT;

    uint32_t a[32][2];
    #pragma unroll
    for (int t = 0; t < 32; t++) { a[t][0] = 0u; a[t][1] = 0u; }

    #pragma unroll
    for (int j = 0; j < 3; j++) {              // K = 48
        float2 v00 = *reinterpret_cast<const float2*>(x0 + 16 * j + cb);
        float2 v10 = *reinterpret_cast<const float2*>(x1 + 16 * j + cb);
        float2 v01 = *reinterpret_cast<const float2*>(x0 + 16 * j + cb + 8);
        float2 v11 = *reinterpret_cast<const float2*>(x1 + 16 * j + cb + 8);
        uint32_t A0 = pk2(v00.x, v00.y), A1 = pk2(v10.x, v10.y);
        uint32_t A2 = pk2(v01.x, v01.y), A3 = pk2(v11.x, v11.y);
        #pragma unroll
        for (int t = 0; t < 32; t += 2) {
            uint32_t B0, B1, B2, B3;
            ldsm_x4(B0, B1, B2, B3, wbp + (uint32_t)t * (8 * 112) + 32 * j);
            mma_f16acc(a[t],     A0, A1, A2, A3, B0, B1);
            mma_f16acc(a[t + 1], A0, A1, A2, A3, B2, B3);
        }
    }

    uint32_t* out = reinterpret_cast<uint32_t*>(g_PQ);   // 128 half2-words per node row
    #pragma unroll
    for (int t = 0; t < 32; t++) {
        if (r0 < NNODES) out[(size_t)r0 * 128 + 4 * t + (l & 3)] = a[t][0];
        if (r1 < NNODES) out[(size_t)r1 * 128 + 4 * t + (l & 3)] = a[t][1];
    }
}

__global__ void __launch_bounds__(256, 1)
gnn_fused_kernel(const float* __restrict__ x, const int* __restrict__ ei32,
                 const float* __restrict__ efeat,
                 const float* __restrict__ W1, const float* __restrict__ b1,
                 const float* __restrict__ W2, const float* __restrict__ b2,
                 const float* __restrict__ W3, const float* __restrict__ b3) {
    extern __shared__ char smem[];
    const uint32_t sb = smem_to_u32(smem);
    const int tid = threadIdx.x;
    const int w = tid >> 5;
    const int l = tid & 31;
    const long long stride = (long long)g_stride;

    // ---- one-time init: zero weight tiles (pad columns must be 0) ----
    for (int i = tid; i < (SM_STAGE - SM_W1C) / 16; i += 256)
        reinterpret_cast<uint4*>(smem + SM_W1C)[i] = make_uint4(0, 0, 0, 0);
    __syncthreads();

    // W1c^T: 128 n-rows x 16 k (W1 rows 96..111), stride 48B
    for (int idx = tid; idx < 128 * 16; idx += 256) {
        int k = idx >> 7, n = idx & 127;
        *reinterpret_cast<__half*>(smem + SM_W1C + n * WCSTRIDE + k * 2) =
            __float2half(W1[(96 + k) * HID + n]);
    }
    // W2^T, W3^T as before
    for (int idx = tid; idx < HID * HID; idx += 256) {
        int k = idx >> 7, n = idx & 127;
        *reinterpret_cast<__half*>(smem + SM_W2 + n * ESTRIDE + k * 2) = __float2half(W2[idx]);
    }
    for (int idx = tid; idx < HID * NFEAT; idx += 256) {
        int k = idx / NFEAT, n = idx - k * NFEAT;
        *reinterpret_cast<__half*>(smem + SM_W3 + n * ESTRIDE + k * 2) = __float2half(W3[idx]);
    }
    if (tid < 64) {
        reinterpret_cast<__half2*>(smem + SM_HB1)[tid] =
            __floats2half2_rn(b1[2 * tid], b1[2 * tid + 1]);
        reinterpret_cast<__half2*>(smem + SM_HB2)[tid] =
            __floats2half2_rn(b2[2 * tid], b2[2 * tid + 1]);
    }
    if (tid < NFEAT) reinterpret_cast<float*>(smem + SM_B3)[tid] = b3[tid];
    __syncthreads();

    // ldmatrix B addressing (x4 over TWO n-tiles)
    const uint32_t woff4 = (uint32_t)(l & 7) * ESTRIDE + (((l >> 3) & 1) << 4)
                         + (uint32_t)(l >> 4) * (8 * ESTRIDE);
    const uint32_t wb2 = sb + SM_W2 + woff4;
    const uint32_t wb3 = sb + SM_W3 + woff4;
    const uint32_t wbc = sb + SM_W1C + (uint32_t)(l & 7) * WCSTRIDE + (((l >> 3) & 1) << 4)
                       + (uint32_t)(l >> 4) * (8 * WCSTRIDE);

    // Stage addressing for this lane's fragment coords
    const int cb = 2 * (l & 3);
    const uint32_t rowb = sb + SM_STAGE + (uint32_t)(16 * w + (l >> 2)) * SSTRIDE;
    const uint32_t stP = rowb + (uint32_t)(l & 3) * 4;          // P half2 words, +t*16
    const uint32_t stE = rowb + 512 + (uint32_t)cb * 4;         // ef f32 section
    const uint32_t hb1a = sb + SM_HB1 + (uint32_t)(l & 3) * 4;
    const uint32_t hb2a = sb + SM_HB2 + (uint32_t)(l & 3) * 4;
    const uint32_t b3a = sb + SM_B3 + (uint32_t)cb * 4;

    // ---- prologue: indices + gather for first tile ----
    int cur = 0;
    {
        long long e = (long long)blockIdx.x * 128 + tid;
        if (tid < 128) {
            int s = ei32[stride * e];
            int t = ei32[stride * (NEDGES + e)];
            reinterpret_cast<int*>(smem + SM_SRC0)[tid] = min(max(s, 0), NNODES - 1);
            reinterpret_cast<int*>(smem + SM_TGT0)[tid] = min(max(t, 0), NNODES - 1);
        }
        __syncthreads();
        issue_gather(sb, reinterpret_cast<const int*>(smem + SM_SRC0),
                     reinterpret_cast<const int*>(smem + SM_TGT0),
                     efeat, (long long)blockIdx.x * 128, tid);
        asm volatile("cp.async.commit_group;" ::: "memory");
    }

    for (int tile = blockIdx.x; tile < NTILES; tile += gridDim.x) {
        const int next = tile + gridDim.x;
        const int* sTgtC = reinterpret_cast<const int*>(smem + (cur ? SM_TGT1 : SM_TGT0));
        int* sSrcN = reinterpret_cast<int*>(smem + (cur ? SM_SRC0 : SM_SRC1));
        int* sTgtN = reinterpret_cast<int*>(smem + (cur ? SM_TGT0 : SM_TGT1));

        // ---- stage ready ----
        asm volatile("cp.async.wait_group 0;" ::: "memory");
        __syncthreads();

        // ---- prefetch next tile's indices ----
        int nsrc = 0, ntgt = 0;
        if (next < NTILES && tid < 128) {
            long long e = (long long)next * 128 + tid;
            nsrc = ei32[stride * e];
            ntgt = ei32[stride * (NEDGES + e)];
        }

        // ---- Layer 1: h1 = relu(P[src] + Q[tgt] + b1 + ef @ W1c^T) ----
        uint32_t a1[16][2];
        #pragma unroll
        for (int t = 0; t < 16; t++) {
            uint32_t hb = lds_b32(hb1a + t * 16);
            uint32_t p0 = lds_b32(stP + t * 16);
            uint32_t q0 = lds_b32(stP + 256 + t * 16);
            uint32_t p1 = lds_b32(stP + 8 * SSTRIDE + t * 16);
            uint32_t q1 = lds_b32(stP + 8 * SSTRIDE + 256 + t * 16);
            a1[t][0] = hadd2u(hadd2u(p0, q0), hb);
            a1[t][1] = hadd2u(hadd2u(p1, q1), hb);
        }
        {   // single K=16 MMA step over ef
            float2 v00 = lds_v2(stE);
            float2 v10 = lds_v2(stE + 8 * SSTRIDE);
            float2 v01 = lds_v2(stE + 32);
            float2 v11 = lds_v2(stE + 8 * SSTRIDE + 32);
            uint32_t A0 = pk2(v00.x, v00.y), A1 = pk2(v10.x, v10.y);
            uint32_t A2 = pk2(v01.x, v01.y), A3 = pk2(v11.x, v11.y);
            #pragma unroll
            for (int t = 0; t < 16; t += 2) {
                uint32_t B0, B1, B2, B3;
                ldsm_x4(B0, B1, B2, B3, wbc + (uint32_t)t * (8 * WCSTRIDE));
                mma_f16acc(a1[t],     A0, A1, A2, A3, B0, B1);
                mma_f16acc(a1[t + 1], A0, A1, A2, A3, B2, B3);
            }
        }
        uint32_t h1[32];
        #pragma unroll
        for (int t = 0; t < 16; t++) {
            h1[2 * t]     = relu2(a1[t][0]);
            h1[2 * t + 1] = relu2(a1[t][1]);
        }

        // ---- store next indices, sync (stage free), kick off next gather ----
        if (next < NTILES && tid < 128) {
            sSrcN[tid] = min(max(nsrc, 0), NNODES - 1);
            sTgtN[tid] = min(max(ntgt, 0), NNODES - 1);
        }
        __syncthreads();
        if (next < NTILES)
            issue_gather(sb, sSrcN, sTgtN, efeat, (long long)next * 128, tid);
        asm volatile("cp.async.commit_group;" ::: "memory");

        // ---- Layer 2: h2 = relu(h1 @ W2^T + b2); f16 accumulators ----
        uint32_t a2[16][2];
        #pragma unroll
        for (int t = 0; t < 16; t++) {
            uint32_t hb = lds_b32(hb2a + t * 16);
            a2[t][0] = hb; a2[t][1] = hb;
        }
        #pragma unroll
        for (int j = 0; j < 8; j++) {
            #pragma unroll
            for (int t = 0; t < 16; t += 2) {
                uint32_t B0, B1, B2, B3;
                ldsm_x4(B0, B1, B2, B3, wb2 + (uint32_t)t * (8 * ESTRIDE) + 32 * j);
                mma_f16acc(a2[t],     h1[4 * j], h1[4 * j + 1], h1[4 * j + 2], h1[4 * j + 3], B0, B1);
                mma_f16acc(a2[t + 1], h1[4 * j], h1[4 * j + 1], h1[4 * j + 2], h1[4 * j + 3], B2, B3);
            }
        }
        uint32_t h2[32];
        #pragma unroll
        for (int t = 0; t < 16; t++) {
            h2[2 * t]     = relu2(a2[t][0]);
            h2[2 * t + 1] = relu2(a2[t][1]);
        }

        // ---- Layer 3: msg = h2 @ W3^T + b3 (N = 48); f32 accumulators ----
        float a3[6][4];
        #pragma unroll
        for (int t = 0; t < 6; t++) {
            float2 bv = lds_v2(b3a + t * 32);
            a3[t][0] = bv.x; a3[t][1] = bv.y; a3[t][2] = bv.x; a3[t][3] = bv.y;
        }
        #pragma unroll
        for (int j = 0; j < 8; j++) {
            #pragma unroll
            for (int t = 0; t < 6; t += 2) {
                uint32_t B0, B1, B2, B3;
                ldsm_x4(B0, B1, B2, B3, wb3 + (uint32_t)t * (8 * ESTRIDE) + 32 * j);
                mma_f16(a3[t],     h2[4 * j], h2[4 * j + 1], h2[4 * j + 2], h2[4 * j + 3], B0, B1);
                mma_f16(a3[t + 1], h2[4 * j], h2[4 * j + 1], h2[4 * j + 2], h2[4 * j + 3], B2, B3);
            }
        }

        // ---- direct register scatter: rows r0=(16w + l>>2), r1=r0+8 ----
        {
            int r0 = 16 * w + (l >> 2), r1 = r0 + 8;
            int tgt0 = sTgtC[r0], tgt1 = sTgtC[r1];
            float* d0 = g_msum + (size_t)tgt0 * NFEAT + cb;
            float* d1 = g_msum + (size_t)tgt1 * NFEAT + cb;
            #pragma unroll
            for (int t = 0; t < 6; t++) {
                red_add_v2(d0 + 8 * t, a3[t][0], a3[t][1]);
                red_add_v2(d1 + 8 * t, a3[t][2], a3[t][3]);
            }
            if ((l & 3) == 0) {
                asm volatile("red.global.add.f32 [%0], %1;" :: "l"(g_cnt + tgt0), "f"(1.0f) : "memory");
                asm volatile("red.global.add.f32 [%0], %1;" :: "l"(g_cnt + tgt1), "f"(1.0f) : "memory");
            }
        }
        cur ^= 1;
    }
}

__global__ void finalize_kernel(const float* __restrict__ x, float* __restrict__ out) {
    int i = blockIdx.x * blockDim.x + threadIdx.x;
    int n4 = NNODES * NFEAT / 4;
    if (i < n4) {
        int node = i / 12;   // 12 float4 per node (48 feats)
        float inv = __fdividef(1.0f, fmaxf(g_cnt[node], 1.0f));
        float4 m = reinterpret_cast<const float4*>(g_msum)[i];
        float4 xv = reinterpret_cast<const float4*>(x)[i];
        float4 o;
        o.x = xv.x + m.x * inv;
        o.y = xv.y + m.y * inv;
        o.z = xv.z + m.z * inv;
        o.w = xv.w + m.w * inv;
        reinterpret_cast<float4*>(out)[i] = o;
    }
}

// ---------------- launch ----------------
extern "C" void kernel_launch(void* const* d_in, const int* in_sizes, int n_in,
                              void* d_out, int out_size) {
    const float* x  = (const float*)d_in[0];
    const int*   ei = (const int*)d_in[1];
    const float* ef = (const float*)d_in[2];
    const float* W1 = (const float*)d_in[3];
    const float* b1 = (const float*)d_in[4];
    const float* W2 = (const float*)d_in[5];
    const float* b2 = (const float*)d_in[6];
    const float* W3 = (const float*)d_in[7];
    const float* b3 = (const float*)d_in[8];

    cudaFuncSetAttribute(gnn_fused_kernel,
                         cudaFuncAttributeMaxDynamicSharedMemorySize, SMEM_TOTAL);

    zero_detect_kernel<<<1024, 256>>>(ei);
    precompute_kernel<<<(NNODES + 127) / 128, 256>>>(x, W1);
    gnn_fused_kernel<<<148, 256, SMEM_TOTAL>>>(x, ei, ef, W1, b1, W2, b2, W3, b3);
    finalize_kernel<<<(NNODES * NFEAT / 4 + 255) / 256, 256>>>(x, (float*)d_out);
}

// round 12
// speedup vs baseline: 2.4965x; 1.1248x over previous
#include <cuda_runtime.h>
#include <cuda_fp16.h>
#include <cstdint>

#define NNODES 100000
#define NEDGES 1600000
#define NFEAT 48
#define HID 128
#define TILE 256
#define NTILES (NEDGES / TILE)   // 6250 exactly

// Scratch (no allocation allowed)
__device__ float g_msum[(size_t)NNODES * NFEAT];          // 19.2MB
__device__ float g_cnt[NNODES];
__device__ int g_stride;   // edge_index word stride: 2 = int64 storage, 1 = int32
__device__ __align__(16) __half g_PQ[(size_t)NNODES * 256];  // 51.2MB: per node [P(128h) | Q(128h)]

// ---------------- SMEM layout (bytes), main kernel ----------------
#define ESTRIDE 272               // W2/W3 rows: 128 fp16 padded +16B (conflict-free ldsm)
#define WCSTRIDE 48               // W1c rows: 16 fp16 (32B) padded to 48B
#define SSTRIDE 592               // stage row: P 256B | Q 256B | ef 64B | pad 16B
#define SM_SRC0 0                 // 256 x int32
#define SM_TGT0 1024
#define SM_SRC1 2048
#define SM_TGT1 3072
#define SM_HB1  4096              // 64 x half2 packed bias b1 (256B)
#define SM_HB2  4352              // 64 x half2 packed bias b2 (256B)
#define SM_B3   4608              // 48 x f32 (256B slot)
#define SM_W1C  4864                        // 128 rows x WCSTRIDE = 6144
#define SM_W2   (SM_W1C + 128 * WCSTRIDE)   // 11008
#define SM_W3   (SM_W2 + 128 * ESTRIDE)     // 45824 (48 rows)
#define SM_STAGE (SM_W3 + 48 * ESTRIDE)     // 58880
#define SMEM_TOTAL (SM_STAGE + TILE * SSTRIDE)   // 210432 bytes

// ---------------- helpers ----------------
__device__ __forceinline__ uint32_t smem_to_u32(const void* p) {
    uint32_t a;
    asm("{ .reg .u64 t; cvta.to.shared.u64 t, %1; cvt.u32.u64 %0, t; }" : "=r"(a) : "l"(p));
    return a;
}

__device__ __forceinline__ void ldsm_x4(uint32_t& r0, uint32_t& r1, uint32_t& r2, uint32_t& r3,
                                        uint32_t addr) {
    asm volatile("ldmatrix.sync.aligned.m8n8.x4.shared.b16 {%0,%1,%2,%3}, [%4];"
                 : "=r"(r0), "=r"(r1), "=r"(r2), "=r"(r3) : "r"(addr));
}

// f32-accumulator MMA (layer 3)
__device__ __forceinline__ void mma_f16(float c[4], uint32_t a0, uint32_t a1, uint32_t a2,
                                        uint32_t a3, uint32_t b0, uint32_t b1) {
    asm volatile(
        "mma.sync.aligned.m16n8k16.row.col.f32.f16.f16.f32 "
        "{%0,%1,%2,%3}, {%4,%5,%6,%7}, {%8,%9}, {%0,%1,%2,%3};"
        : "+f"(c[0]), "+f"(c[1]), "+f"(c[2]), "+f"(c[3])
        : "r"(a0), "r"(a1), "r"(a2), "r"(a3), "r"(b0), "r"(b1));
}

// f16-accumulator MMA: C regs are packed half2, same coords as A-frags
__device__ __forceinline__ void mma_f16acc(uint32_t c[2], uint32_t a0, uint32_t a1, uint32_t a2,
                                           uint32_t a3, uint32_t b0, uint32_t b1) {
    asm volatile(
        "mma.sync.aligned.m16n8k16.row.col.f16.f16.f16.f16 "
        "{%0,%1}, {%2,%3,%4,%5}, {%6,%7}, {%0,%1};"
        : "+r"(c[0]), "+r"(c[1])
        : "r"(a0), "r"(a1), "r"(a2), "r"(a3), "r"(b0), "r"(b1));
}

__device__ __forceinline__ uint32_t pk2(float a, float b) {
    __half2 h = __floats2half2_rn(a, b);
    return *reinterpret_cast<uint32_t*>(&h);
}

__device__ __forceinline__ uint32_t relu2(uint32_t p) {
    uint32_t r;
    asm("max.f16x2 %0, %1, %2;" : "=r"(r) : "r"(p), "r"(0u));
    return r;
}

__device__ __forceinline__ uint32_t hadd2u(uint32_t a, uint32_t b) {
    uint32_t r;
    asm("add.f16x2 %0, %1, %2;" : "=r"(r) : "r"(a), "r"(b));
    return r;
}

__device__ __forceinline__ float2 lds_v2(uint32_t addr) {
    float2 v;
    asm volatile("ld.shared.v2.f32 {%0, %1}, [%2];" : "=f"(v.x), "=f"(v.y) : "r"(addr));
    return v;
}

__device__ __forceinline__ uint32_t lds_b32(uint32_t addr) {
    uint32_t v;
    asm volatile("ld.shared.b32 %0, [%1];" : "=r"(v) : "r"(addr));
    return v;
}

__device__ __forceinline__ void red_add_v2(float* p, float a, float b) {
    asm volatile("red.global.add.v2.f32 [%0], {%1, %2};"
                 :: "l"(p), "f"(a), "f"(b) : "memory");
}

__device__ __forceinline__ void cp16(uint32_t dst, const void* src) {
    asm volatile("cp.async.cg.shared.global [%0], [%1], 16;" :: "r"(dst), "l"(src) : "memory");
}

// Gather one tile: P[src] (16x16B) | Q[tgt] (16x16B) | ef (4x16B) per row, contiguous in stage.
__device__ __forceinline__ void issue_gather(uint32_t sb, const int* sSrc, const int* sTgt,
                                             const float* efeat, long long base, int tid) {
    const char* pqb = reinterpret_cast<const char*>(g_PQ);
    #pragma unroll
    for (int j = 0; j < 18; j++) {           // 256 rows * 36 chunks / 512 threads
        int f = j * 512 + tid;
        int row = f / 36;
        int q = f - row * 36;
        const void* src;
        if (q < 32) {
            int node = (q < 16) ? sSrc[row] : sTgt[row];
            src = pqb + (size_t)node * 512 + q * 16;
        } else {
            src = reinterpret_cast<const char*>(efeat) + (size_t)(base + row) * 64 + (q - 32) * 16;
        }
        cp16(sb + SM_STAGE + row * SSTRIDE + q * 16, src);
    }
}

// ---------------- kernels ----------------

// zero scratch + detect edge_index width (int64 vs downcast int32; see R3 notes).
__global__ void zero_detect_kernel(const int* __restrict__ ei32) {
    if (blockIdx.x == 0 && threadIdx.x == 0) {
        int odd_or = 0;
        #pragma unroll 8
        for (int i = 0; i < 256; i++) odd_or |= ei32[2 * i + 1];
        g_stride = odd_or ? 1 : 2;
    }
    int n4 = NNODES * NFEAT / 4;
    float4 z = make_float4(0.f, 0.f, 0.f, 0.f);
    for (int i = blockIdx.x * blockDim.x + threadIdx.x; i < n4; i += gridDim.x * blockDim.x) {
        reinterpret_cast<float4*>(g_msum)[i] = z;
        if (i < NNODES) g_cnt[i] = 0.0f;
    }
}

// Precompute PQ[n] = [ x[n] @ W1[0:48] , x[n] @ W1[48:96] ]  (fp16, f16 accum)
__global__ void __launch_bounds__(256, 1)
precompute_kernel(const float* __restrict__ x, const float* __restrict__ W1) {
    __shared__ __align__(16) char smw[256 * 112];   // Wt: 256 n-rows x 48 k fp16, stride 112B
    const int tid = threadIdx.x;
    const int w = tid >> 5;
    const int l = tid & 31;

    for (int idx = tid; idx < 256 * 48; idx += 256) {
        int n = idx / 48, k = idx - n * 48;
        float v = (n < 128) ? W1[k * HID + n] : W1[(48 + k) * HID + (n - 128)];
        *reinterpret_cast<__half*>(smw + n * 112 + k * 2) = __float2half(v);
    }
    __syncthreads();

    const uint32_t sbw = smem_to_u32(smw);
    const uint32_t wbp = sbw + (uint32_t)(l & 7) * 112 + (((l >> 3) & 1) << 4)
                       + (uint32_t)(l >> 4) * (8 * 112);
    const int cb = 2 * (l & 3);
    int r0 = blockIdx.x * 128 + 16 * w + (l >> 2);
    int r1 = r0 + 8;
    int r0c = min(r0, NNODES - 1), r1c = min(r1, NNODES - 1);
    const float* x0 = x + (size_t)r0c * NFEAT;
    const float* x1 = x + (size_t)r1c * NFEAT;

    uint32_t a[32][2];
    #pragma unroll
    for (int t = 0; t < 32; t++) { a[t][0] = 0u; a[t][1] = 0u; }

    #pragma unroll
    for (int j = 0; j < 3; j++) {              // K = 48
        float2 v00 = *reinterpret_cast<const float2*>(x0 + 16 * j + cb);
        float2 v10 = *reinterpret_cast<const float2*>(x1 + 16 * j + cb);
        float2 v01 = *reinterpret_cast<const float2*>(x0 + 16 * j + cb + 8);
        float2 v11 = *reinterpret_cast<const float2*>(x1 + 16 * j + cb + 8);
        uint32_t A0 = pk2(v00.x, v00.y), A1 = pk2(v10.x, v10.y);
        uint32_t A2 = pk2(v01.x, v01.y), A3 = pk2(v11.x, v11.y);
        #pragma unroll
        for (int t = 0; t < 32; t += 2) {
            uint32_t B0, B1, B2, B3;
            ldsm_x4(B0, B1, B2, B3, wbp + (uint32_t)t * (8 * 112) + 32 * j);
            mma_f16acc(a[t],     A0, A1, A2, A3, B0, B1);
            mma_f16acc(a[t + 1], A0, A1, A2, A3, B2, B3);
        }
    }

    uint32_t* out = reinterpret_cast<uint32_t*>(g_PQ);   // 128 half2-words per node row
    #pragma unroll
    for (int t = 0; t < 32; t++) {
        if (r0 < NNODES) out[(size_t)r0 * 128 + 4 * t + (l & 3)] = a[t][0];
        if (r1 < NNODES) out[(size_t)r1 * 128 + 4 * t + (l & 3)] = a[t][1];
    }
}

__global__ void __launch_bounds__(512, 1)
gnn_fused_kernel(const float* __restrict__ x, const int* __restrict__ ei32,
                 const float* __restrict__ efeat,
                 const float* __restrict__ W1, const float* __restrict__ b1,
                 const float* __restrict__ W2, const float* __restrict__ b2,
                 const float* __restrict__ W3, const float* __restrict__ b3) {
    extern __shared__ char smem[];
    const uint32_t sb = smem_to_u32(smem);
    const int tid = threadIdx.x;
    const int w = tid >> 5;            // 0..15
    const int l = tid & 31;
    const long long stride = (long long)g_stride;

    // ---- one-time init: zero weight tiles (pad columns must be 0) ----
    for (int i = tid; i < (SM_STAGE - SM_W1C) / 16; i += 512)
        reinterpret_cast<uint4*>(smem + SM_W1C)[i] = make_uint4(0, 0, 0, 0);
    __syncthreads();

    // W1c^T: 128 n-rows x 16 k (W1 rows 96..111), stride 48B
    for (int idx = tid; idx < 128 * 16; idx += 512) {
        int k = idx >> 7, n = idx & 127;
        *reinterpret_cast<__half*>(smem + SM_W1C + n * WCSTRIDE + k * 2) =
            __float2half(W1[(96 + k) * HID + n]);
    }
    for (int idx = tid; idx < HID * HID; idx += 512) {
        int k = idx >> 7, n = idx & 127;
        *reinterpret_cast<__half*>(smem + SM_W2 + n * ESTRIDE + k * 2) = __float2half(W2[idx]);
    }
    for (int idx = tid; idx < HID * NFEAT; idx += 512) {
        int k = idx / NFEAT, n = idx - k * NFEAT;
        *reinterpret_cast<__half*>(smem + SM_W3 + n * ESTRIDE + k * 2) = __float2half(W3[idx]);
    }
    if (tid < 64) {
        reinterpret_cast<__half2*>(smem + SM_HB1)[tid] =
            __floats2half2_rn(b1[2 * tid], b1[2 * tid + 1]);
        reinterpret_cast<__half2*>(smem + SM_HB2)[tid] =
            __floats2half2_rn(b2[2 * tid], b2[2 * tid + 1]);
    }
    if (tid < NFEAT) reinterpret_cast<float*>(smem + SM_B3)[tid] = b3[tid];
    __syncthreads();

    // ldmatrix B addressing (x4 over TWO n-tiles)
    const uint32_t woff4 = (uint32_t)(l & 7) * ESTRIDE + (((l >> 3) & 1) << 4)
                         + (uint32_t)(l >> 4) * (8 * ESTRIDE);
    const uint32_t wb2 = sb + SM_W2 + woff4;
    const uint32_t wb3 = sb + SM_W3 + woff4;
    const uint32_t wbc = sb + SM_W1C + (uint32_t)(l & 7) * WCSTRIDE + (((l >> 3) & 1) << 4)
                       + (uint32_t)(l >> 4) * (8 * WCSTRIDE);

    // Stage addressing for this lane's fragment coords (rows 16w + l>>2, +8)
    const int cb = 2 * (l & 3);
    const uint32_t rowb = sb + SM_STAGE + (uint32_t)(16 * w + (l >> 2)) * SSTRIDE;
    const uint32_t stP = rowb + (uint32_t)(l & 3) * 4;
    const uint32_t stE = rowb + 512 + (uint32_t)cb * 4;
    const uint32_t hb1a = sb + SM_HB1 + (uint32_t)(l & 3) * 4;
    const uint32_t hb2a = sb + SM_HB2 + (uint32_t)(l & 3) * 4;
    const uint32_t b3a = sb + SM_B3 + (uint32_t)cb * 4;

    // ---- prologue: indices + gather for first tile ----
    int cur = 0;
    {
        long long e = (long long)blockIdx.x * TILE + tid;
        if (tid < TILE) {
            int s = ei32[stride * e];
            int t = ei32[stride * (NEDGES + e)];
            reinterpret_cast<int*>(smem + SM_SRC0)[tid] = min(max(s, 0), NNODES - 1);
            reinterpret_cast<int*>(smem + SM_TGT0)[tid] = min(max(t, 0), NNODES - 1);
        }
        __syncthreads();
        issue_gather(sb, reinterpret_cast<const int*>(smem + SM_SRC0),
                     reinterpret_cast<const int*>(smem + SM_TGT0),
                     efeat, (long long)blockIdx.x * TILE, tid);
        asm volatile("cp.async.commit_group;" ::: "memory");
    }

    for (int tile = blockIdx.x; tile < NTILES; tile += gridDim.x) {
        const int next = tile + gridDim.x;
        const int* sTgtC = reinterpret_cast<const int*>(smem + (cur ? SM_TGT1 : SM_TGT0));
        int* sSrcN = reinterpret_cast<int*>(smem + (cur ? SM_SRC0 : SM_SRC1));
        int* sTgtN = reinterpret_cast<int*>(smem + (cur ? SM_TGT0 : SM_TGT1));

        // ---- stage ready ----
        asm volatile("cp.async.wait_group 0;" ::: "memory");
        __syncthreads();

        // ---- prefetch next tile's indices ----
        int nsrc = 0, ntgt = 0;
        if (next < NTILES && tid < TILE) {
            long long e = (long long)next * TILE + tid;
            nsrc = ei32[stride * e];
            ntgt = ei32[stride * (NEDGES + e)];
        }

        // ---- Layer 1: h1 = relu(P[src] + Q[tgt] + b1 + ef @ W1c^T) ----
        uint32_t a1[16][2];
        #pragma unroll
        for (int t = 0; t < 16; t++) {
            uint32_t hb = lds_b32(hb1a + t * 16);
            uint32_t p0 = lds_b32(stP + t * 16);
            uint32_t q0 = lds_b32(stP + 256 + t * 16);
            uint32_t p1 = lds_b32(stP + 8 * SSTRIDE + t * 16);
            uint32_t q1 = lds_b32(stP + 8 * SSTRIDE + 256 + t * 16);
            a1[t][0] = hadd2u(hadd2u(p0, q0), hb);
            a1[t][1] = hadd2u(hadd2u(p1, q1), hb);
        }
        {   // single K=16 MMA step over ef
            float2 v00 = lds_v2(stE);
            float2 v10 = lds_v2(stE + 8 * SSTRIDE);
            float2 v01 = lds_v2(stE + 32);
            float2 v11 = lds_v2(stE + 8 * SSTRIDE + 32);
            uint32_t A0 = pk2(v00.x, v00.y), A1 = pk2(v10.x, v10.y);
            uint32_t A2 = pk2(v01.x, v01.y), A3 = pk2(v11.x, v11.y);
            #pragma unroll
            for (int t = 0; t < 16; t += 2) {
                uint32_t B0, B1, B2, B3;
                ldsm_x4(B0, B1, B2, B3, wbc + (uint32_t)t * (8 * WCSTRIDE));
                mma_f16acc(a1[t],     A0, A1, A2, A3, B0, B1);
                mma_f16acc(a1[t + 1], A0, A1, A2, A3, B2, B3);
            }
        }
        uint32_t h1[32];
        #pragma unroll
        for (int t = 0; t < 16; t++) {
            h1[2 * t]     = relu2(a1[t][0]);
            h1[2 * t + 1] = relu2(a1[t][1]);
        }

        // ---- store next indices, sync (stage free), kick off next gather ----
        if (next < NTILES && tid < TILE) {
            sSrcN[tid] = min(max(nsrc, 0), NNODES - 1);
            sTgtN[tid] = min(max(ntgt, 0), NNODES - 1);
        }
        __syncthreads();
        if (next < NTILES)
            issue_gather(sb, sSrcN, sTgtN, efeat, (long long)next * TILE, tid);
        asm volatile("cp.async.commit_group;" ::: "memory");

        // ---- Layer 2: h2 = relu(h1 @ W2^T + b2); f16 accumulators ----
        uint32_t a2[16][2];
        #pragma unroll
        for (int t = 0; t < 16; t++) {
            uint32_t hb = lds_b32(hb2a + t * 16);
            a2[t][0] = hb; a2[t][1] = hb;
        }
        #pragma unroll
        for (int j = 0; j < 8; j++) {
            #pragma unroll
            for (int t = 0; t < 16; t += 2) {
                uint32_t B0, B1, B2, B3;
                ldsm_x4(B0, B1, B2, B3, wb2 + (uint32_t)t * (8 * ESTRIDE) + 32 * j);
                mma_f16acc(a2[t],     h1[4 * j], h1[4 * j + 1], h1[4 * j + 2], h1[4 * j + 3], B0, B1);
                mma_f16acc(a2[t + 1], h1[4 * j], h1[4 * j + 1], h1[4 * j + 2], h1[4 * j + 3], B2, B3);
            }
        }
        uint32_t h2[32];
        #pragma unroll
        for (int t = 0; t < 16; t++) {
            h2[2 * t]     = relu2(a2[t][0]);
            h2[2 * t + 1] = relu2(a2[t][1]);
        }

        // ---- Layer 3: msg = h2 @ W3^T + b3 (N = 48); f32 accumulators ----
        float a3[6][4];
        #pragma unroll
        for (int t = 0; t < 6; t++) {
            float2 bv = lds_v2(b3a + t * 32);
            a3[t][0] = bv.x; a3[t][1] = bv.y; a3[t][2] = bv.x; a3[t][3] = bv.y;
        }
        #pragma unroll
        for (int j = 0; j < 8; j++) {
            #pragma unroll
            for (int t = 0; t < 6; t += 2) {
                uint32_t B0, B1, B2, B3;
                ldsm_x4(B0, B1, B2, B3, wb3 + (uint32_t)t * (8 * ESTRIDE) + 32 * j);
                mma_f16(a3[t],     h2[4 * j], h2[4 * j + 1], h2[4 * j + 2], h2[4 * j + 3], B0, B1);
                mma_f16(a3[t + 1], h2[4 * j], h2[4 * j + 1], h2[4 * j + 2], h2[4 * j + 3], B2, B3);
            }
        }

        // ---- direct register scatter: rows r0=(16w + l>>2), r1=r0+8 ----
        {
            int r0 = 16 * w + (l >> 2), r1 = r0 + 8;
            int tgt0 = sTgtC[r0], tgt1 = sTgtC[r1];
            float* d0 = g_msum + (size_t)tgt0 * NFEAT + cb;
            float* d1 = g_msum + (size_t)tgt1 * NFEAT + cb;
            #pragma unroll
            for (int t = 0; t < 6; t++) {
                red_add_v2(d0 + 8 * t, a3[t][0], a3[t][1]);
                red_add_v2(d1 + 8 * t, a3[t][2], a3[t][3]);
            }
            if ((l & 3) == 0) {
                asm volatile("red.global.add.f32 [%0], %1;" :: "l"(g_cnt + tgt0), "f"(1.0f) : "memory");
                asm volatile("red.global.add.f32 [%0], %1;" :: "l"(g_cnt + tgt1), "f"(1.0f) : "memory");
            }
        }
        cur ^= 1;
    }
}

__global__ void finalize_kernel(const float* __restrict__ x, float* __restrict__ out) {
    int i = blockIdx.x * blockDim.x + threadIdx.x;
    int n4 = NNODES * NFEAT / 4;
    if (i < n4) {
        int node = i / 12;   // 12 float4 per node (48 feats)
        float inv = __fdividef(1.0f, fmaxf(g_cnt[node], 1.0f));
        float4 m = reinterpret_cast<const float4*>(g_msum)[i];
        float4 xv = reinterpret_cast<const float4*>(x)[i];
        float4 o;
        o.x = xv.x + m.x * inv;
        o.y = xv.y + m.y * inv;
        o.z = xv.z + m.z * inv;
        o.w = xv.w + m.w * inv;
        reinterpret_cast<float4*>(out)[i] = o;
    }
}

// ---------------- launch ----------------
extern "C" void kernel_launch(void* const* d_in, const int* in_sizes, int n_in,
                              void* d_out, int out_size) {
    const float* x  = (const float*)d_in[0];
    const int*   ei = (const int*)d_in[1];
    const float* ef = (const float*)d_in[2];
    const float* W1 = (const float*)d_in[3];
    const float* b1 = (const float*)d_in[4];
    const float* W2 = (const float*)d_in[5];
    const float* b2 = (const float*)d_in[6];
    const float* W3 = (const float*)d_in[7];
    const float* b3 = (const float*)d_in[8];

    cudaFuncSetAttribute(gnn_fused_kernel,
                         cudaFuncAttributeMaxDynamicSharedMemorySize, SMEM_TOTAL);

    zero_detect_kernel<<<1024, 256>>>(ei);
    precompute_kernel<<<(NNODES + 127) / 128, 256>>>(x, W1);
    gnn_fused_kernel<<<148, 512, SMEM_TOTAL>>>(x, ei, ef, W1, b1, W2, b2, W3, b3);
    finalize_kernel<<<(NNODES * NFEAT / 4 + 255) / 256, 256>>>(x, (float*)d_out);
}

// round 14
// speedup vs baseline: 2.5441x; 1.0191x over previous
#include <cuda_runtime.h>
#include <cuda_fp16.h>
#include <cstdint>

#define NNODES 100000
#define NEDGES 1600000
#define NFEAT 48
#define HID 128
#define TILE 256
#define NTILES (NEDGES / TILE)   // 6250 exactly
#define PRE_BLOCKS 782           // ceil(100000/128) precompute blocks

// Scratch (no allocation allowed)
__device__ float g_msum[(size_t)NNODES * NFEAT];          // 19.2MB
__device__ float g_cnt[NNODES];
__device__ int g_stride;   // edge_index word stride: 2 = int64 storage, 1 = int32
__device__ __align__(16) __half g_PQ[(size_t)NNODES * 256];  // 51.2MB: per node [P(128h) | Q(128h)]

// ---------------- SMEM layout (bytes), main kernel ----------------
#define ESTRIDE 272               // W2/W3 rows: 128 fp16 padded +16B (conflict-free ldsm)
#define WCSTRIDE 48               // W1c rows: 16 fp16 (32B) padded to 48B
#define SSTRIDE 592               // stage row: P 256B | Q 256B | ef 64B | pad 16B
#define SM_SRC0 0                 // 256 x int32
#define SM_TGT0 1024
#define SM_SRC1 2048
#define SM_TGT1 3072
#define SM_HB1  4096              // 64 x half2 packed bias b1 (256B)
#define SM_HB2  4352              // 64 x half2 packed bias b2 (256B)
#define SM_B3   4608              // 48 x f32 (256B slot)
#define SM_W1C  4864                        // 128 rows x WCSTRIDE = 6144
#define SM_W2   (SM_W1C + 128 * WCSTRIDE)   // 11008
#define SM_W3   (SM_W2 + 128 * ESTRIDE)     // 45824 (48 rows)
#define SM_STAGE (SM_W3 + 48 * ESTRIDE)     // 58880
#define SMEM_TOTAL (SM_STAGE + TILE * SSTRIDE)   // 210432 bytes

// ---------------- helpers ----------------
__device__ __forceinline__ uint32_t smem_to_u32(const void* p) {
    uint32_t a;
    asm("{ .reg .u64 t; cvta.to.shared.u64 t, %1; cvt.u32.u64 %0, t; }" : "=r"(a) : "l"(p));
    return a;
}

__device__ __forceinline__ void ldsm_x4(uint32_t& r0, uint32_t& r1, uint32_t& r2, uint32_t& r3,
                                        uint32_t addr) {
    asm volatile("ldmatrix.sync.aligned.m8n8.x4.shared.b16 {%0,%1,%2,%3}, [%4];"
                 : "=r"(r0), "=r"(r1), "=r"(r2), "=r"(r3) : "r"(addr));
}

// f32-accumulator MMA (layer 3)
__device__ __forceinline__ void mma_f16(float c[4], uint32_t a0, uint32_t a1, uint32_t a2,
                                        uint32_t a3, uint32_t b0, uint32_t b1) {
    asm volatile(
        "mma.sync.aligned.m16n8k16.row.col.f32.f16.f16.f32 "
        "{%0,%1,%2,%3}, {%4,%5,%6,%7}, {%8,%9}, {%0,%1,%2,%3};"
        : "+f"(c[0]), "+f"(c[1]), "+f"(c[2]), "+f"(c[3])
        : "r"(a0), "r"(a1), "r"(a2), "r"(a3), "r"(b0), "r"(b1));
}

// f16-accumulator MMA: C regs are packed half2, same coords as A-frags
__device__ __forceinline__ void mma_f16acc(uint32_t c[2], uint32_t a0, uint32_t a1, uint32_t a2,
                                           uint32_t a3, uint32_t b0, uint32_t b1) {
    asm volatile(
        "mma.sync.aligned.m16n8k16.row.col.f16.f16.f16.f16 "
        "{%0,%1}, {%2,%3,%4,%5}, {%6,%7}, {%0,%1};"
        : "+r"(c[0]), "+r"(c[1])
        : "r"(a0), "r"(a1), "r"(a2), "r"(a3), "r"(b0), "r"(b1));
}

__device__ __forceinline__ uint32_t pk2(float a, float b) {
    __half2 h = __floats2half2_rn(a, b);
    return *reinterpret_cast<uint32_t*>(&h);
}

__device__ __forceinline__ uint32_t relu2(uint32_t p) {
    uint32_t r;
    asm("max.f16x2 %0, %1, %2;" : "=r"(r) : "r"(p), "r"(0u));
    return r;
}

__device__ __forceinline__ uint32_t hadd2u(uint32_t a, uint32_t b) {
    uint32_t r;
    asm("add.f16x2 %0, %1, %2;" : "=r"(r) : "r"(a), "r"(b));
    return r;
}

__device__ __forceinline__ float2 lds_v2(uint32_t addr) {
    float2 v;
    asm volatile("ld.shared.v2.f32 {%0, %1}, [%2];" : "=f"(v.x), "=f"(v.y) : "r"(addr));
    return v;
}

__device__ __forceinline__ uint32_t lds_b32(uint32_t addr) {
    uint32_t v;
    asm volatile("ld.shared.b32 %0, [%1];" : "=r"(v) : "r"(addr));
    return v;
}

__device__ __forceinline__ void red_add_v2(float* p, float a, float b) {
    asm volatile("red.global.add.v2.f32 [%0], {%1, %2};"
                 :: "l"(p), "f"(a), "f"(b) : "memory");
}

__device__ __forceinline__ void cp16(uint32_t dst, const void* src) {
    asm volatile("cp.async.cg.shared.global [%0], [%1], 16;" :: "r"(dst), "l"(src) : "memory");
}

// Gather one tile: P[src] (16x16B) | Q[tgt] (16x16B) | ef (4x16B) per row, contiguous in stage.
__device__ __forceinline__ void issue_gather(uint32_t sb, const int* sSrc, const int* sTgt,
                                             const float* efeat, long long base, int tid) {
    const char* pqb = reinterpret_cast<const char*>(g_PQ);
    #pragma unroll
    for (int j = 0; j < 18; j++) {           // 256 rows * 36 chunks / 512 threads
        int f = j * 512 + tid;
        int row = f / 36;
        int q = f - row * 36;
        const void* src;
        if (q < 32) {
            int node = (q < 16) ? sSrc[row] : sTgt[row];
            src = pqb + (size_t)node * 512 + q * 16;
        } else {
            src = reinterpret_cast<const char*>(efeat) + (size_t)(base + row) * 64 + (q - 32) * 16;
        }
        cp16(sb + SM_STAGE + row * SSTRIDE + q * 16, src);
    }
}

// ---------------- kernels ----------------

// Merged init: blocks [0, PRE_BLOCKS) compute PQ[n] = [x@W1a | x@W1b];
// blocks [PRE_BLOCKS, grid) zero msum/cnt; first zero block also detects ei width.
__global__ void __launch_bounds__(256, 1)
init_kernel(const float* __restrict__ x, const float* __restrict__ W1,
            const int* __restrict__ ei32) {
    const int tid = threadIdx.x;

    if (blockIdx.x >= PRE_BLOCKS) {
        // ---- zero + detect path ----
        if (blockIdx.x == PRE_BLOCKS && tid == 0) {
            int odd_or = 0;
            #pragma unroll 8
            for (int i = 0; i < 256; i++) odd_or |= ei32[2 * i + 1];
            g_stride = odd_or ? 1 : 2;
        }
        int nblk = gridDim.x - PRE_BLOCKS;
        int bid = blockIdx.x - PRE_BLOCKS;
        int n4 = NNODES * NFEAT / 4;
        float4 z = make_float4(0.f, 0.f, 0.f, 0.f);
        for (int i = bid * 256 + tid; i < n4; i += nblk * 256) {
            reinterpret_cast<float4*>(g_msum)[i] = z;
            if (i < NNODES) g_cnt[i] = 0.0f;
        }
        return;
    }

    // ---- precompute path ----
    __shared__ __align__(16) char smw[256 * 112];   // Wt: 256 n-rows x 48 k fp16, stride 112B
    const int w = tid >> 5;
    const int l = tid & 31;

    for (int idx = tid; idx < 256 * 48; idx += 256) {
        int n = idx / 48, k = idx - n * 48;
        float v = (n < 128) ? W1[k * HID + n] : W1[(48 + k) * HID + (n - 128)];
        *reinterpret_cast<__half*>(smw + n * 112 + k * 2) = __float2half(v);
    }
    __syncthreads();

    const uint32_t sbw = smem_to_u32(smw);
    const uint32_t wbp = sbw + (uint32_t)(l & 7) * 112 + (((l >> 3) & 1) << 4)
                       + (uint32_t)(l >> 4) * (8 * 112);
    const int cb = 2 * (l & 3);
    int r0 = blockIdx.x * 128 + 16 * w + (l >> 2);
    int r1 = r0 + 8;
    int r0c = min(r0, NNODES - 1), r1c = min(r1, NNODES - 1);
    const float* x0 = x + (size_t)r0c * NFEAT;
    const float* x1 = x + (size_t)r1c * NFEAT;

    uint32_t a[32][2];
    #pragma unroll
    for (int t = 0; t < 32; t++) { a[t][0] = 0u; a[t][1] = 0u; }

    #pragma unroll
    for (int j = 0; j < 3; j++) {              // K = 48
        float2 v00 = *reinterpret_cast<const float2*>(x0 + 16 * j + cb);
        float2 v10 = *reinterpret_cast<const float2*>(x1 + 16 * j + cb);
        float2 v01 = *reinterpret_cast<const float2*>(x0 + 16 * j + cb + 8);
        float2 v11 = *reinterpret_cast<const float2*>(x1 + 16 * j + cb + 8);
        uint32_t A0 = pk2(v00.x, v00.y), A1 = pk2(v10.x, v10.y);
        uint32_t A2 = pk2(v01.x, v01.y), A3 = pk2(v11.x, v11.y);
        #pragma unroll
        for (int t = 0; t < 32; t += 2) {
            uint32_t B0, B1, B2, B3;
            ldsm_x4(B0, B1, B2, B3, wbp + (uint32_t)t * (8 * 112) + 32 * j);
            mma_f16acc(a[t],     A0, A1, A2, A3, B0, B1);
            mma_f16acc(a[t + 1], A0, A1, A2, A3, B2, B3);
        }
    }

    uint32_t* out = reinterpret_cast<uint32_t*>(g_PQ);   // 128 half2-words per node row
    #pragma unroll
    for (int t = 0; t < 32; t++) {
        if (r0 < NNODES) out[(size_t)r0 * 128 + 4 * t + (l & 3)] = a[t][0];
        if (r1 < NNODES) out[(size_t)r1 * 128 + 4 * t + (l & 3)] = a[t][1];
    }
}

__global__ void __launch_bounds__(512, 1)
gnn_fused_kernel(const float* __restrict__ x, const int* __restrict__ ei32,
                 const float* __restrict__ efeat,
                 const float* __restrict__ W1, const float* __restrict__ b1,
                 const float* __restrict__ W2, const float* __restrict__ b2,
                 const float* __restrict__ W3, const float* __restrict__ b3) {
    extern __shared__ char smem[];
    const uint32_t sb = smem_to_u32(smem);
    const int tid = threadIdx.x;
    const int w = tid >> 5;            // 0..15
    const int l = tid & 31;
    const long long stride = (long long)g_stride;

    // ---- one-time init: zero weight tiles (pad columns must be 0) ----
    for (int i = tid; i < (SM_STAGE - SM_W1C) / 16; i += 512)
        reinterpret_cast<uint4*>(smem + SM_W1C)[i] = make_uint4(0, 0, 0, 0);
    __syncthreads();

    // W1c^T: 128 n-rows x 16 k (W1 rows 96..111), stride 48B
    for (int idx = tid; idx < 128 * 16; idx += 512) {
        int k = idx >> 7, n = idx & 127;
        *reinterpret_cast<__half*>(smem + SM_W1C + n * WCSTRIDE + k * 2) =
            __float2half(W1[(96 + k) * HID + n]);
    }
    for (int idx = tid; idx < HID * HID; idx += 512) {
        int k = idx >> 7, n = idx & 127;
        *reinterpret_cast<__half*>(smem + SM_W2 + n * ESTRIDE + k * 2) = __float2half(W2[idx]);
    }
    for (int idx = tid; idx < HID * NFEAT; idx += 512) {
        int k = idx / NFEAT, n = idx - k * NFEAT;
        *reinterpret_cast<__half*>(smem + SM_W3 + n * ESTRIDE + k * 2) = __float2half(W3[idx]);
    }
    if (tid < 64) {
        reinterpret_cast<__half2*>(smem + SM_HB1)[tid] =
            __floats2half2_rn(b1[2 * tid], b1[2 * tid + 1]);
        reinterpret_cast<__half2*>(smem + SM_HB2)[tid] =
            __floats2half2_rn(b2[2 * tid], b2[2 * tid + 1]);
    }
    if (tid < NFEAT) reinterpret_cast<float*>(smem + SM_B3)[tid] = b3[tid];
    __syncthreads();

    // ldmatrix B addressing (x4 over TWO n-tiles)
    const uint32_t woff4 = (uint32_t)(l & 7) * ESTRIDE + (((l >> 3) & 1) << 4)
                         + (uint32_t)(l >> 4) * (8 * ESTRIDE);
    const uint32_t wb2 = sb + SM_W2 + woff4;
    const uint32_t wb3 = sb + SM_W3 + woff4;
    const uint32_t wbc = sb + SM_W1C + (uint32_t)(l & 7) * WCSTRIDE + (((l >> 3) & 1) << 4)
                       + (uint32_t)(l >> 4) * (8 * WCSTRIDE);

    // Stage addressing for this lane's fragment coords (rows 16w + l>>2, +8)
    const int cb = 2 * (l & 3);
    const uint32_t rowb = sb + SM_STAGE + (uint32_t)(16 * w + (l >> 2)) * SSTRIDE;
    const uint32_t stP = rowb + (uint32_t)(l & 3) * 4;
    const uint32_t stE = rowb + 512 + (uint32_t)cb * 4;
    const uint32_t hb1a = sb + SM_HB1 + (uint32_t)(l & 3) * 4;
    const uint32_t hb2a = sb + SM_HB2 + (uint32_t)(l & 3) * 4;
    const uint32_t b3a = sb + SM_B3 + (uint32_t)cb * 4;

    // ---- prologue: indices + gather for first tile ----
    int cur = 0;
    {
        long long e = (long long)blockIdx.x * TILE + tid;
        if (tid < TILE) {
            int s = ei32[stride * e];
            int t = ei32[stride * (NEDGES + e)];
            reinterpret_cast<int*>(smem + SM_SRC0)[tid] = min(max(s, 0), NNODES - 1);
            reinterpret_cast<int*>(smem + SM_TGT0)[tid] = min(max(t, 0), NNODES - 1);
        }
        __syncthreads();
        issue_gather(sb, reinterpret_cast<const int*>(smem + SM_SRC0),
                     reinterpret_cast<const int*>(smem + SM_TGT0),
                     efeat, (long long)blockIdx.x * TILE, tid);
        asm volatile("cp.async.commit_group;" ::: "memory");
    }

    for (int tile = blockIdx.x; tile < NTILES; tile += gridDim.x) {
        const int next = tile + gridDim.x;
        const int* sTgtC = reinterpret_cast<const int*>(smem + (cur ? SM_TGT1 : SM_TGT0));
        int* sSrcN = reinterpret_cast<int*>(smem + (cur ? SM_SRC0 : SM_SRC1));
        int* sTgtN = reinterpret_cast<int*>(smem + (cur ? SM_TGT0 : SM_TGT1));

        // ---- stage ready ----
        asm volatile("cp.async.wait_group 0;" ::: "memory");
        __syncthreads();

        // ---- prefetch next tile's indices ----
        int nsrc = 0, ntgt = 0;
        if (next < NTILES && tid < TILE) {
            long long e = (long long)next * TILE + tid;
            nsrc = ei32[stride * e];
            ntgt = ei32[stride * (NEDGES + e)];
        }

        // ---- Layer 1: h1 = relu(P[src] + Q[tgt] + b1 + ef @ W1c^T) ----
        uint32_t a1[16][2];
        #pragma unroll
        for (int t = 0; t < 16; t++) {
            uint32_t hb = lds_b32(hb1a + t * 16);
            uint32_t p0 = lds_b32(stP + t * 16);
            uint32_t q0 = lds_b32(stP + 256 + t * 16);
            uint32_t p1 = lds_b32(stP + 8 * SSTRIDE + t * 16);
            uint32_t q1 = lds_b32(stP + 8 * SSTRIDE + 256 + t * 16);
            a1[t][0] = hadd2u(hadd2u(p0, q0), hb);
            a1[t][1] = hadd2u(hadd2u(p1, q1), hb);
        }
        {   // single K=16 MMA step over ef
            float2 v00 = lds_v2(stE);
            float2 v10 = lds_v2(stE + 8 * SSTRIDE);
            float2 v01 = lds_v2(stE + 32);
            float2 v11 = lds_v2(stE + 8 * SSTRIDE + 32);
            uint32_t A0 = pk2(v00.x, v00.y), A1 = pk2(v10.x, v10.y);
            uint32_t A2 = pk2(v01.x, v01.y), A3 = pk2(v11.x, v11.y);
            #pragma unroll
            for (int t = 0; t < 16; t += 2) {
                uint32_t B0, B1, B2, B3;
                ldsm_x4(B0, B1, B2, B3, wbc + (uint32_t)t * (8 * WCSTRIDE));
                mma_f16acc(a1[t],     A0, A1, A2, A3, B0, B1);
                mma_f16acc(a1[t + 1], A0, A1, A2, A3, B2, B3);
            }
        }
        uint32_t h1[32];
        #pragma unroll
        for (int t = 0; t < 16; t++) {
            h1[2 * t]     = relu2(a1[t][0]);
            h1[2 * t + 1] = relu2(a1[t][1]);
        }

        // ---- store next indices, sync (stage free), kick off next gather ----
        if (next < NTILES && tid < TILE) {
            sSrcN[tid] = min(max(nsrc, 0), NNODES - 1);
            sTgtN[tid] = min(max(ntgt, 0), NNODES - 1);
        }
        __syncthreads();
        if (next < NTILES)
            issue_gather(sb, sSrcN, sTgtN, efeat, (long long)next * TILE, tid);
        asm volatile("cp.async.commit_group;" ::: "memory");

        // ---- Fused Layers 2+3: per t-pair, finish a2 then immediately feed L3 ----
        // L3 accumulators (f32) init with bias
        float a3[6][4];
        #pragma unroll
        for (int u = 0; u < 6; u++) {
            float2 bv = lds_v2(b3a + u * 32);
            a3[u][0] = bv.x; a3[u][1] = bv.y; a3[u][2] = bv.x; a3[u][3] = bv.y;
        }
        #pragma unroll
        for (int t = 0; t < 16; t += 2) {       // t-pair = L3 k-step t/2
            uint32_t hb = lds_b32(hb2a + t * 16);
            uint32_t hb_1 = lds_b32(hb2a + (t + 1) * 16);
            uint32_t c0[2] = {hb, hb};
            uint32_t c1[2] = {hb_1, hb_1};
            #pragma unroll
            for (int j = 0; j < 8; j++) {
                uint32_t B0, B1, B2, B3;
                ldsm_x4(B0, B1, B2, B3, wb2 + (uint32_t)t * (8 * ESTRIDE) + 32 * j);
                mma_f16acc(c0, h1[4 * j], h1[4 * j + 1], h1[4 * j + 2], h1[4 * j + 3], B0, B1);
                mma_f16acc(c1, h1[4 * j], h1[4 * j + 1], h1[4 * j + 2], h1[4 * j + 3], B2, B3);
            }
            uint32_t H0 = relu2(c0[0]), H1 = relu2(c0[1]);
            uint32_t H2 = relu2(c1[0]), H3 = relu2(c1[1]);
            #pragma unroll
            for (int u = 0; u < 6; u += 2) {
                uint32_t B0, B1, B2, B3;
                ldsm_x4(B0, B1, B2, B3, wb3 + (uint32_t)u * (8 * ESTRIDE) + 32 * (t / 2));
                mma_f16(a3[u],     H0, H1, H2, H3, B0, B1);
                mma_f16(a3[u + 1], H0, H1, H2, H3, B2, B3);
            }
        }

        // ---- direct register scatter: rows r0=(16w + l>>2), r1=r0+8 ----
        {
            int r0 = 16 * w + (l >> 2), r1 = r0 + 8;
            int tgt0 = sTgtC[r0], tgt1 = sTgtC[r1];
            float* d0 = g_msum + (size_t)tgt0 * NFEAT + cb;
            float* d1 = g_msum + (size_t)tgt1 * NFEAT + cb;
            #pragma unroll
            for (int u = 0; u < 6; u++) {
                red_add_v2(d0 + 8 * u, a3[u][0], a3[u][1]);
                red_add_v2(d1 + 8 * u, a3[u][2], a3[u][3]);
            }
            if ((l & 3) == 0) {
                asm volatile("red.global.add.f32 [%0], %1;" :: "l"(g_cnt + tgt0), "f"(1.0f) : "memory");
                asm volatile("red.global.add.f32 [%0], %1;" :: "l"(g_cnt + tgt1), "f"(1.0f) : "memory");
            }
        }
        cur ^= 1;
    }
}

__global__ void finalize_kernel(const float* __restrict__ x, float* __restrict__ out) {
    int i = blockIdx.x * blockDim.x + threadIdx.x;
    int n4 = NNODES * NFEAT / 4;
    if (i < n4) {
        int node = i / 12;   // 12 float4 per node (48 feats)
        float inv = __fdividef(1.0f, fmaxf(g_cnt[node], 1.0f));
        float4 m = reinterpret_cast<const float4*>(g_msum)[i];
        float4 xv = reinterpret_cast<const float4*>(x)[i];
        float4 o;
        o.x = xv.x + m.x * inv;
        o.y = xv.y + m.y * inv;
        o.z = xv.z + m.z * inv;
        o.w = xv.w + m.w * inv;
        reinterpret_cast<float4*>(out)[i] = o;
    }
}

// ---------------- launch ----------------
extern "C" void kernel_launch(void* const* d_in, const int* in_sizes, int n_in,
                              void* d_out, int out_size) {
    const float* x  = (const float*)d_in[0];
    const int*   ei = (const int*)d_in[1];
    const float* ef = (const float*)d_in[2];
    const float* W1 = (const float*)d_in[3];
    const float* b1 = (const float*)d_in[4];
    const float* W2 = (const float*)d_in[5];
    const float* b2 = (const float*)d_in[6];
    const float* W3 = (const float*)d_in[7];
    const float* b3 = (const float*)d_in[8];

    cudaFuncSetAttribute(gnn_fused_kernel,
                         cudaFuncAttributeMaxDynamicSharedMemorySize, SMEM_TOTAL);

    init_kernel<<<PRE_BLOCKS + 882, 256>>>(x, W1, ei);
    gnn_fused_kernel<<<148, 512, SMEM_TOTAL>>>(x, ei, ef, W1, b1, W2, b2, W3, b3);
    finalize_kernel<<<(NNODES * NFEAT / 4 + 255) / 256, 256>>>(x, (float*)d_out);
}